// round 1
// baseline (speedup 1.0000x reference)
#include <cuda_runtime.h>
#include <math.h>
#include <stdint.h>

// Problem constants
#define Bb 128
#define Tt 400
#define Hh 512
#define H2 1024
#define Ee 128
#define Vv 50000

// Output layout (concatenated reference tuple, row-major each)
#define OFF_FINAL 0L
#define OFF_H     6400000L
#define OFF_C     6465536L
#define OFF_CT    6531072L
#define OFF_ATTN  6662144L
#define OFF_PGEN  6713344L
#define OFF_COV   6713472L

// Scratch (device globals: allowed; no runtime allocation)
__device__ float g_yemb[Bb * Ee];
__device__ float g_x[Bb * Ee];
__device__ float g_gates[Bb * 4 * Hh];
__device__ float g_decfea[Bb * H2];
__device__ float g_scores[Bb * Tt];
__device__ float g_o1[Bb * Hh];
__device__ float g_logits[(size_t)Bb * Vv];

__device__ __forceinline__ float tanh_fast(float x) {
    float y;
    asm("tanh.approx.f32 %0, %1;" : "=f"(y) : "f"(x));
    return y;
}
__device__ __forceinline__ float sigmoid_fast(float x) {
    return 1.0f / (1.0f + __expf(-x));
}

// ---------------------------------------------------------------------------
// Embedding gather: g_yemb[b,e] = emb[y[b], e]
// ---------------------------------------------------------------------------
__global__ void embed_kernel(const int* __restrict__ y, const float* __restrict__ emb,
                             float* __restrict__ out) {
    int i = blockIdx.x * blockDim.x + threadIdx.x;   // 0 .. B*E
    if (i >= Bb * Ee) return;
    int b = i >> 7;        // /128
    int e = i & 127;
    out[i] = emb[(size_t)y[b] * Ee + e];
}

// ---------------------------------------------------------------------------
// Generic GEMM: C[128,N] (+)= A1[128,K1] @ W1[N,K1]^T + A2[128,K2] @ W2[N,K2]^T + bias
// BM=128 BN=64 BK=16, 256 threads, 8x4 register tile.
// K-split across gridDim.y with atomicAdd accumulate (caller zeroes C).
// ---------------------------------------------------------------------------
#define BM 128
#define BN 64
#define BK 16

__global__ __launch_bounds__(256) void gemm_bt(
    const float* __restrict__ A1, int lda1, int K1,
    const float* __restrict__ W1, int ldw1,
    const float* __restrict__ A2, int lda2, int K2,
    const float* __restrict__ W2, int ldw2,
    const float* __restrict__ bias1, const float* __restrict__ bias2,
    float* __restrict__ C, int N, int kchunk, int split)
{
    __shared__ __align__(16) float As[BK][BM + 4];
    __shared__ __align__(16) float Ws[BK][BN + 4];

    int tid = threadIdx.x;
    int tx = tid & 15;          // N micro index (x4)
    int ty = tid >> 4;          // M micro index (x8)
    int bn0 = blockIdx.x * BN;

    int steps_total = (K1 + K2) >> 4;
    int s0 = blockIdx.y * kchunk;
    int s1 = min(s0 + kchunk, steps_total);
    if (s0 >= steps_total) return;

    float acc[8][4];
#pragma unroll
    for (int i = 0; i < 8; i++)
#pragma unroll
        for (int j = 0; j < 4; j++) acc[i][j] = 0.0f;

    int a_row = tid >> 2;          // 0..63
    int a_c4 = (tid & 3) * 4;      // 0,4,8,12

    for (int s = s0; s < s1; ++s) {
        int kk = s << 4;
        const float* Ap; int lda; int ko;
        const float* Wp; int ldw;
        if (kk < K1) { Ap = A1; lda = lda1; ko = kk;      Wp = W1; ldw = ldw1; }
        else         { Ap = A2; lda = lda2; ko = kk - K1; Wp = W2; ldw = ldw2; }

        // A tile: 128x16 floats, 2 float4 per thread
        {
            float4 v = *(const float4*)&Ap[(size_t)a_row * lda + ko + a_c4];
            As[a_c4 + 0][a_row] = v.x; As[a_c4 + 1][a_row] = v.y;
            As[a_c4 + 2][a_row] = v.z; As[a_c4 + 3][a_row] = v.w;
            int r2 = a_row + 64;
            float4 v2 = *(const float4*)&Ap[(size_t)r2 * lda + ko + a_c4];
            As[a_c4 + 0][r2] = v2.x; As[a_c4 + 1][r2] = v2.y;
            As[a_c4 + 2][r2] = v2.z; As[a_c4 + 3][r2] = v2.w;
        }
        // W tile: 64x16 floats, 1 float4 per thread (guard N tail)
        {
            int n = a_row;
            float4 v = make_float4(0.f, 0.f, 0.f, 0.f);
            if (bn0 + n < N)
                v = *(const float4*)&Wp[(size_t)(bn0 + n) * ldw + ko + a_c4];
            Ws[a_c4 + 0][n] = v.x; Ws[a_c4 + 1][n] = v.y;
            Ws[a_c4 + 2][n] = v.z; Ws[a_c4 + 3][n] = v.w;
        }
        __syncthreads();

#pragma unroll
        for (int k = 0; k < BK; k++) {
            float4 a0 = *(const float4*)&As[k][ty * 8];
            float4 a1 = *(const float4*)&As[k][ty * 8 + 4];
            float4 w  = *(const float4*)&Ws[k][tx * 4];
            float am[8] = {a0.x, a0.y, a0.z, a0.w, a1.x, a1.y, a1.z, a1.w};
            float wn[4] = {w.x, w.y, w.z, w.w};
#pragma unroll
            for (int i = 0; i < 8; i++)
#pragma unroll
                for (int j = 0; j < 4; j++) acc[i][j] += am[i] * wn[j];
        }
        __syncthreads();
    }

    bool addb = (blockIdx.y == 0);
#pragma unroll
    for (int i = 0; i < 8; i++) {
        int m = ty * 8 + i;
#pragma unroll
        for (int j = 0; j < 4; j++) {
            int n = bn0 + tx * 4 + j;
            if (n < N) {
                float v = acc[i][j];
                if (addb) {
                    if (bias1) v += bias1[n];
                    if (bias2) v += bias2[n];
                }
                if (split) atomicAdd(&C[(size_t)m * N + n], v);
                else       C[(size_t)m * N + n] = v;
            }
        }
    }
}

// ---------------------------------------------------------------------------
// LSTM elementwise: gates[B,4H] (order i,f,g,o) -> h,c written to d_out
// ---------------------------------------------------------------------------
__global__ void lstm_kernel(const float* __restrict__ gates, const float* __restrict__ c0,
                            float* __restrict__ out) {
    int idx = blockIdx.x * blockDim.x + threadIdx.x;   // 0..B*H
    if (idx >= Bb * Hh) return;
    int b = idx >> 9;
    int h = idx & 511;
    const float* g = gates + (size_t)b * 4 * Hh;
    float gi = g[h], gf = g[512 + h], gg = g[1024 + h], go = g[1536 + h];
    float c = sigmoid_fast(gf) * c0[idx] + sigmoid_fast(gi) * tanhf(gg);
    float hh = sigmoid_fast(go) * tanhf(c);
    out[OFF_H + idx] = hh;
    out[OFF_C + idx] = c;
}

// ---------------------------------------------------------------------------
// Attention scores: scores[b,t] = sum_n v[n]*tanh(ef[b,t,n] + dec[b,n] + cov[b,t]*Wc[n])
// Block: 8 warps = 8 t's for one b. grid (50, 128)
// ---------------------------------------------------------------------------
__global__ __launch_bounds__(256) void scores_kernel(
    const float* __restrict__ ef, const float* __restrict__ dec,
    const float* __restrict__ vw, const float* __restrict__ Wc,
    const float* __restrict__ cov, float* __restrict__ scores)
{
    __shared__ __align__(16) float s_dec[H2];
    __shared__ __align__(16) float s_v[H2];
    __shared__ __align__(16) float s_wc[H2];
    int b = blockIdx.y;
    int tid = threadIdx.x;
    for (int i = tid; i < H2; i += 256) {
        s_dec[i] = dec[(size_t)b * H2 + i];
        s_v[i] = vw[i];
        s_wc[i] = Wc[i];
    }
    __syncthreads();

    int warp = tid >> 5, lane = tid & 31;
    int t = blockIdx.x * 8 + warp;      // 50*8 = 400 exact
    float cv = cov[(size_t)b * Tt + t];
    const float* p = ef + ((size_t)b * Tt + t) * H2;

    float acc = 0.0f;
#pragma unroll
    for (int i = 0; i < 8; i++) {
        int n = i * 128 + lane * 4;
        float4 e4 = *(const float4*)(p + n);
        acc += tanh_fast(e4.x + s_dec[n]     + cv * s_wc[n])     * s_v[n];
        acc += tanh_fast(e4.y + s_dec[n + 1] + cv * s_wc[n + 1]) * s_v[n + 1];
        acc += tanh_fast(e4.z + s_dec[n + 2] + cv * s_wc[n + 2]) * s_v[n + 2];
        acc += tanh_fast(e4.w + s_dec[n + 3] + cv * s_wc[n + 3]) * s_v[n + 3];
    }
#pragma unroll
    for (int o = 16; o > 0; o >>= 1) acc += __shfl_down_sync(0xffffffffu, acc, o);
    if (lane == 0) scores[(size_t)b * Tt + t] = acc;
}

// ---------------------------------------------------------------------------
// Softmax over T + mask renorm + coverage update. Block per b, 256 threads.
// ---------------------------------------------------------------------------
__global__ void softmaxT_kernel(const float* __restrict__ scores, const float* __restrict__ mask,
                                const float* __restrict__ cov, float* __restrict__ out)
{
    __shared__ float sm[256];
    int b = blockIdx.x, tid = threadIdx.x;
    int t0 = tid, t1 = tid + 256;
    float s0 = (t0 < Tt) ? scores[(size_t)b * Tt + t0] : -1e30f;
    float s1 = (t1 < Tt) ? scores[(size_t)b * Tt + t1] : -1e30f;

    sm[tid] = fmaxf(s0, s1); __syncthreads();
    for (int s = 128; s > 0; s >>= 1) { if (tid < s) sm[tid] = fmaxf(sm[tid], sm[tid + s]); __syncthreads(); }
    float m = sm[0]; __syncthreads();

    float e0 = (t0 < Tt) ? __expf(s0 - m) : 0.f;
    float e1 = (t1 < Tt) ? __expf(s1 - m) : 0.f;
    sm[tid] = e0 + e1; __syncthreads();
    for (int s = 128; s > 0; s >>= 1) { if (tid < s) sm[tid] += sm[tid + s]; __syncthreads(); }
    float S = sm[0]; __syncthreads();

    float a0 = (t0 < Tt) ? (e0 / S) * mask[(size_t)b * Tt + t0] : 0.f;
    float a1 = (t1 < Tt) ? (e1 / S) * mask[(size_t)b * Tt + t1] : 0.f;
    sm[tid] = a0 + a1; __syncthreads();
    for (int s = 128; s > 0; s >>= 1) { if (tid < s) sm[tid] += sm[tid + s]; __syncthreads(); }
    float S2 = sm[0] + 1e-12f;

    if (t0 < Tt) {
        float a = a0 / S2;
        out[OFF_ATTN + (size_t)b * Tt + t0] = a;
        out[OFF_COV  + (size_t)b * Tt + t0] = cov[(size_t)b * Tt + t0] + a;
    }
    if (t1 < Tt) {
        float a = a1 / S2;
        out[OFF_ATTN + (size_t)b * Tt + t1] = a;
        out[OFF_COV  + (size_t)b * Tt + t1] = cov[(size_t)b * Tt + t1] + a;
    }
}

// ---------------------------------------------------------------------------
// c_t[b,n] = sum_t attn[b,t] * eo[b,t,n]. grid (2, 128), 512 threads.
// ---------------------------------------------------------------------------
__global__ __launch_bounds__(512) void ct_kernel(const float* __restrict__ eo,
                                                 const float* __restrict__ out_ro,
                                                 float* __restrict__ out)
{
    __shared__ float sa[Tt];
    int b = blockIdx.y;
    int n = blockIdx.x * 512 + threadIdx.x;
    if (threadIdx.x < Tt) sa[threadIdx.x] = out_ro[OFF_ATTN + (size_t)b * Tt + threadIdx.x];
    __syncthreads();
    const float* p = eo + (size_t)b * Tt * H2 + n;
    float acc = 0.0f;
#pragma unroll 4
    for (int t = 0; t < Tt; t++) acc += sa[t] * p[(size_t)t * H2];
    out[OFF_CT + (size_t)b * H2 + n] = acc;
}

// ---------------------------------------------------------------------------
// p_gen[b] = sigmoid([c_t, h, c, x] . W_pg + b_pg). Block per b, 256 threads.
// ---------------------------------------------------------------------------
__global__ void pgen_kernel(const float* __restrict__ out_ro, const float* __restrict__ x,
                            const float* __restrict__ Wpg, const float* __restrict__ bpg,
                            float* __restrict__ out)
{
    __shared__ float sm[256];
    int b = blockIdx.x, tid = threadIdx.x;
    const float* ct = out_ro + OFF_CT + (size_t)b * H2;
    const float* h  = out_ro + OFF_H  + (size_t)b * Hh;
    const float* c  = out_ro + OFF_C  + (size_t)b * Hh;
    float acc = 0.0f;
    for (int k = tid; k < H2; k += 256) acc += ct[k] * Wpg[k];
    for (int k = tid; k < Hh; k += 256) acc += h[k] * Wpg[1024 + k] + c[k] * Wpg[1536 + k];
    if (tid < Ee) acc += x[(size_t)b * Ee + tid] * Wpg[2048 + tid];
    sm[tid] = acc; __syncthreads();
    for (int s = 128; s > 0; s >>= 1) { if (tid < s) sm[tid] += sm[tid + s]; __syncthreads(); }
    if (tid == 0) out[OFF_PGEN + b] = sigmoid_fast(sm[0] + bpg[0]);
}

// ---------------------------------------------------------------------------
// Vocab softmax, scaled by p_gen, written directly into final_dist region.
// Block per b, 1024 threads.
// ---------------------------------------------------------------------------
__global__ __launch_bounds__(1024) void vsoftmax_kernel(const float* __restrict__ logits,
                                                        float* __restrict__ out)
{
    __shared__ float sm[1024];
    int b = blockIdx.x, tid = threadIdx.x;
    const float* L = logits + (size_t)b * Vv;
    float m = -1e30f;
    for (int j = tid; j < Vv; j += 1024) m = fmaxf(m, L[j]);
    sm[tid] = m; __syncthreads();
    for (int s = 512; s > 0; s >>= 1) { if (tid < s) sm[tid] = fmaxf(sm[tid], sm[tid + s]); __syncthreads(); }
    m = sm[0]; __syncthreads();

    float s = 0.0f;
    for (int j = tid; j < Vv; j += 1024) s += __expf(L[j] - m);
    sm[tid] = s; __syncthreads();
    for (int st = 512; st > 0; st >>= 1) { if (tid < st) sm[tid] += sm[tid + st]; __syncthreads(); }
    float S = sm[0];

    float scale = out[OFF_PGEN + b] / S;
    float* F = out + (size_t)b * Vv;
    for (int j = tid; j < Vv; j += 1024) F[j] = __expf(L[j] - m) * scale;
}

// ---------------------------------------------------------------------------
// Pointer scatter: final[b, ebev[b,t]] += (1 - p_gen[b]) * attn[b,t]
// ---------------------------------------------------------------------------
__global__ void scatter_kernel(const int* __restrict__ ebev, float* __restrict__ out)
{
    int i = blockIdx.x * 256 + threadIdx.x;
    if (i >= Bb * Tt) return;
    int b = i / Tt;
    float pg = out[OFF_PGEN + b];
    float a = out[OFF_ATTN + i];
    atomicAdd(&out[(size_t)b * Vv + ebev[i]], (1.0f - pg) * a);
}

// ---------------------------------------------------------------------------
// Host launch
// ---------------------------------------------------------------------------
static void launch_gemm(const float* A1, int lda1, int K1, const float* W1, int ldw1,
                        const float* A2, int lda2, int K2, const float* W2, int ldw2,
                        const float* b1, const float* b2, float* C, int N, int ksplit)
{
    int steps = (K1 + K2) >> 4;
    int kchunk = (steps + ksplit - 1) / ksplit;
    int ky = (steps + kchunk - 1) / kchunk;
    dim3 grid((N + BN - 1) / BN, ky);
    gemm_bt<<<grid, 256>>>(A1, lda1, K1, W1, ldw1, A2, lda2, K2, W2, ldw2,
                           b1, b2, C, N, kchunk, (ky > 1) ? 1 : 0);
}

extern "C" void kernel_launch(void* const* d_in, const int* in_sizes, int n_in,
                              void* d_out_v, int out_size)
{
    (void)in_sizes; (void)n_in; (void)out_size;
    const int*   y    = (const int*)  d_in[0];
    const float* h0   = (const float*)d_in[1];
    const float* c0   = (const float*)d_in[2];
    const float* ct1  = (const float*)d_in[3];
    const float* eo   = (const float*)d_in[4];
    const float* ef   = (const float*)d_in[5];
    const float* mask = (const float*)d_in[6];
    const int*   ebev = (const int*)  d_in[7];
    const float* cov  = (const float*)d_in[8];
    const float* emb  = (const float*)d_in[9];
    const float* W_c  = (const float*)d_in[10];
    const float* W_dp = (const float*)d_in[11];
    const float* b_dp = (const float*)d_in[12];
    const float* v_w  = (const float*)d_in[13];
    const float* W_xc = (const float*)d_in[14];
    const float* b_xc = (const float*)d_in[15];
    const float* W_ih = (const float*)d_in[16];
    const float* W_hh = (const float*)d_in[17];
    const float* b_ih = (const float*)d_in[18];
    const float* b_hh = (const float*)d_in[19];
    const float* W_pg = (const float*)d_in[20];
    const float* b_pg = (const float*)d_in[21];
    const float* W_o1 = (const float*)d_in[22];
    const float* b_o1 = (const float*)d_in[23];
    const float* W_o2 = (const float*)d_in[24];
    const float* b_o2 = (const float*)d_in[25];
    float* out = (float*)d_out_v;

    float *p_yemb, *p_x, *p_gates, *p_dec, *p_scores, *p_o1, *p_logits;
    cudaGetSymbolAddress((void**)&p_yemb,   g_yemb);
    cudaGetSymbolAddress((void**)&p_x,      g_x);
    cudaGetSymbolAddress((void**)&p_gates,  g_gates);
    cudaGetSymbolAddress((void**)&p_dec,    g_decfea);
    cudaGetSymbolAddress((void**)&p_scores, g_scores);
    cudaGetSymbolAddress((void**)&p_o1,     g_o1);
    cudaGetSymbolAddress((void**)&p_logits, g_logits);

    // 1. embedding gather
    embed_kernel<<<(Bb * Ee + 255) / 256, 256>>>(y, emb, p_yemb);

    // 2. x = [c_t_1 | y_emb] @ W_xc^T + b_xc   (N=128, K=1024+128)
    cudaMemsetAsync(p_x, 0, sizeof(float) * Bb * Ee, 0);
    launch_gemm(ct1, H2, H2, W_xc, 1152,
                p_yemb, Ee, Ee, W_xc + 1024, 1152,
                b_xc, nullptr, p_x, Ee, 36);

    // 3. gates = x @ W_ih^T + h0 @ W_hh^T + b_ih + b_hh   (N=2048, K=128+512)
    cudaMemsetAsync(p_gates, 0, sizeof(float) * Bb * 4 * Hh, 0);
    launch_gemm(p_x, Ee, Ee, W_ih, Ee,
                h0, Hh, Hh, W_hh, Hh,
                b_ih, b_hh, p_gates, 4 * Hh, 8);

    // 4. LSTM cell -> h, c (written straight to d_out)
    lstm_kernel<<<(Bb * Hh + 255) / 256, 256>>>(p_gates, c0, out);

    // 5. dec_fea = [h | c] @ W_dp^T + b_dp   (N=1024, K=512+512)
    cudaMemsetAsync(p_dec, 0, sizeof(float) * Bb * H2, 0);
    launch_gemm(out + OFF_H, Hh, Hh, W_dp, H2,
                out + OFF_C, Hh, Hh, W_dp + 512, H2,
                b_dp, nullptr, p_dec, H2, 8);

    // 6. attention scores
    scores_kernel<<<dim3(Tt / 8, Bb), 256>>>(ef, p_dec, v_w, W_c, cov, p_scores);

    // 7. softmax over T + mask renorm + coverage
    softmaxT_kernel<<<Bb, 256>>>(p_scores, mask, cov, out);

    // 8. c_t = attn @ encoder_outputs
    ct_kernel<<<dim3(2, Bb), 512>>>(eo, out, out);

    // 9. p_gen
    pgen_kernel<<<Bb, 256>>>(out, p_x, W_pg, b_pg, out);

    // 10. o1 = [h | c_t] @ W_o1^T + b_o1   (N=512, K=512+1024)
    cudaMemsetAsync(p_o1, 0, sizeof(float) * Bb * Hh, 0);
    launch_gemm(out + OFF_H, Hh, Hh, W_o1, 3 * Hh,
                out + OFF_CT, H2, H2, W_o1 + 512, 3 * Hh,
                b_o1, nullptr, p_o1, Hh, 16);

    // 11. logits = o1 @ W_o2^T + b_o2   (N=50000, K=512) — no K split
    launch_gemm(p_o1, Hh, Hh, W_o2, Hh,
                nullptr, 0, 0, nullptr, 0,
                b_o2, nullptr, p_logits, Vv, 1);

    // 12. vocab softmax scaled by p_gen -> final_dist region
    vsoftmax_kernel<<<Bb, 1024>>>(p_logits, out);

    // 13. pointer scatter-add
    scatter_kernel<<<(Bb * Tt + 255) / 256, 256>>>(ebev, out);
}

// round 3
// speedup vs baseline: 1.2954x; 1.2954x over previous
#include <cuda_runtime.h>
#include <math.h>
#include <stdint.h>

// Problem constants
#define Bb 128
#define Tt 400
#define Hh 512
#define H2 1024
#define Ee 128
#define Vv 50000

// Output layout (concatenated reference tuple, row-major each)
#define OFF_FINAL 0L
#define OFF_H     6400000L
#define OFF_C     6465536L
#define OFF_CT    6531072L
#define OFF_ATTN  6662144L
#define OFF_PGEN  6713344L
#define OFF_COV   6713472L

// Scratch (device globals: allowed; no runtime allocation)
__device__ float g_yemb[Bb * Ee];
__device__ float g_x[Bb * Ee];
__device__ float g_gates[Bb * 4 * Hh];
__device__ float g_decfea[Bb * H2];
__device__ float g_scores[Bb * Tt];
__device__ float g_o1[Bb * Hh];
__device__ float g_logits[(size_t)Bb * Vv];

__device__ __forceinline__ float tanh_fast(float x) {
    float y;
    asm("tanh.approx.f32 %0, %1;" : "=f"(y) : "f"(x));
    return y;
}
__device__ __forceinline__ float sigmoid_fast(float x) {
    return 1.0f / (1.0f + __expf(-x));
}
__device__ __forceinline__ uint32_t f2tf32(float x) {
    uint32_t r;
    asm("cvt.rna.tf32.f32 %0, %1;" : "=r"(r) : "f"(x));
    return r;
}

// ---------------------------------------------------------------------------
// Embedding gather
// ---------------------------------------------------------------------------
__global__ void embed_kernel(const int* __restrict__ y, const float* __restrict__ emb,
                             float* __restrict__ out) {
    int i = blockIdx.x * blockDim.x + threadIdx.x;
    if (i >= Bb * Ee) return;
    int b = i >> 7;
    int e = i & 127;
    out[i] = emb[(size_t)y[b] * Ee + e];
}

// ---------------------------------------------------------------------------
// Generic small GEMM (FFMA): C[128,N] (+)= A1@W1^T + A2@W2^T + bias, K-split
// ---------------------------------------------------------------------------
#define BM 128
#define BN 64
#define BK 16

__global__ __launch_bounds__(256) void gemm_bt(
    const float* __restrict__ A1, int lda1, int K1,
    const float* __restrict__ W1, int ldw1,
    const float* __restrict__ A2, int lda2, int K2,
    const float* __restrict__ W2, int ldw2,
    const float* __restrict__ bias1, const float* __restrict__ bias2,
    float* __restrict__ C, int N, int kchunk, int split)
{
    __shared__ __align__(16) float As[BK][BM + 4];
    __shared__ __align__(16) float Ws[BK][BN + 4];

    int tid = threadIdx.x;
    int tx = tid & 15;
    int ty = tid >> 4;
    int bn0 = blockIdx.x * BN;

    int steps_total = (K1 + K2) >> 4;
    int s0 = blockIdx.y * kchunk;
    int s1 = min(s0 + kchunk, steps_total);
    if (s0 >= steps_total) return;

    float acc[8][4];
#pragma unroll
    for (int i = 0; i < 8; i++)
#pragma unroll
        for (int j = 0; j < 4; j++) acc[i][j] = 0.0f;

    int a_row = tid >> 2;
    int a_c4 = (tid & 3) * 4;

    for (int s = s0; s < s1; ++s) {
        int kk = s << 4;
        const float* Ap; int lda; int ko;
        const float* Wp; int ldw;
        if (kk < K1) { Ap = A1; lda = lda1; ko = kk;      Wp = W1; ldw = ldw1; }
        else         { Ap = A2; lda = lda2; ko = kk - K1; Wp = W2; ldw = ldw2; }

        {
            float4 v = *(const float4*)&Ap[(size_t)a_row * lda + ko + a_c4];
            As[a_c4 + 0][a_row] = v.x; As[a_c4 + 1][a_row] = v.y;
            As[a_c4 + 2][a_row] = v.z; As[a_c4 + 3][a_row] = v.w;
            int r2 = a_row + 64;
            float4 v2 = *(const float4*)&Ap[(size_t)r2 * lda + ko + a_c4];
            As[a_c4 + 0][r2] = v2.x; As[a_c4 + 1][r2] = v2.y;
            As[a_c4 + 2][r2] = v2.z; As[a_c4 + 3][r2] = v2.w;
        }
        {
            int n = a_row;
            float4 v = make_float4(0.f, 0.f, 0.f, 0.f);
            if (bn0 + n < N)
                v = *(const float4*)&Wp[(size_t)(bn0 + n) * ldw + ko + a_c4];
            Ws[a_c4 + 0][n] = v.x; Ws[a_c4 + 1][n] = v.y;
            Ws[a_c4 + 2][n] = v.z; Ws[a_c4 + 3][n] = v.w;
        }
        __syncthreads();

#pragma unroll
        for (int k = 0; k < BK; k++) {
            float4 a0 = *(const float4*)&As[k][ty * 8];
            float4 a1 = *(const float4*)&As[k][ty * 8 + 4];
            float4 w  = *(const float4*)&Ws[k][tx * 4];
            float am[8] = {a0.x, a0.y, a0.z, a0.w, a1.x, a1.y, a1.z, a1.w};
            float wn[4] = {w.x, w.y, w.z, w.w};
#pragma unroll
            for (int i = 0; i < 8; i++)
#pragma unroll
                for (int j = 0; j < 4; j++) acc[i][j] += am[i] * wn[j];
        }
        __syncthreads();
    }

    bool addb = (blockIdx.y == 0);
#pragma unroll
    for (int i = 0; i < 8; i++) {
        int m = ty * 8 + i;
#pragma unroll
        for (int j = 0; j < 4; j++) {
            int n = bn0 + tx * 4 + j;
            if (n < N) {
                float v = acc[i][j];
                if (addb) {
                    if (bias1) v += bias1[n];
                    if (bias2) v += bias2[n];
                }
                if (split) atomicAdd(&C[(size_t)m * N + n], v);
                else       C[(size_t)m * N + n] = v;
            }
        }
    }
}

// ---------------------------------------------------------------------------
// Vocab GEMM via portable warp-level tensor-core MMA (tf32):
// logits[128, 50000] = o1[128,512] @ W_o2[50000,512]^T + b_o2
// CTA tile: M=128, N=128, K=512 in 16 chunks of BK=32.
// 8 warps (2 M x 4 N), warp tile m64 n32, mma.m16n8k8.tf32, fp32 accum.
// ---------------------------------------------------------------------------
#define VSTRIDE 36   // smem row stride in floats (pad for conflict-free frag loads)

__global__ __launch_bounds__(256) void vocab_gemm_mma(
    const float* __restrict__ A,      // [128,512]
    const float* __restrict__ W,      // [50000,512]
    const float* __restrict__ bias,   // [50000]
    float* __restrict__ Cl)           // [128,50000]
{
    __shared__ __align__(16) float As[128 * VSTRIDE];
    __shared__ __align__(16) float Ws[128 * VSTRIDE];

    int tid = threadIdx.x;
    int lane = tid & 31;
    int wid = tid >> 5;
    int wm = (wid & 1) * 64;     // warp M offset
    int wn = (wid >> 1) * 32;    // warp N offset
    int bn0 = blockIdx.x * 128;

    int grp = lane >> 2;         // 0..7
    int qid = lane & 3;          // 0..3

    float acc[4][4][4];
#pragma unroll
    for (int i = 0; i < 4; i++)
#pragma unroll
        for (int j = 0; j < 4; j++)
#pragma unroll
            for (int r = 0; r < 4; r++) acc[i][j][r] = 0.0f;

    for (int s = 0; s < 16; s++) {
        int ck = s * 32;

        // Global -> smem (convert to tf32 once here)
#pragma unroll
        for (int i = 0; i < 4; i++) {
            int slot = i * 256 + tid;       // 0..1023
            int row = slot >> 3;            // 0..127
            int k4 = (slot & 7) << 2;       // 0..28

            float4 va = *(const float4*)&A[row * 512 + ck + k4];
            uint4 ua = make_uint4(f2tf32(va.x), f2tf32(va.y), f2tf32(va.z), f2tf32(va.w));
            *(uint4*)&As[row * VSTRIDE + k4] = ua;

            int nrow = bn0 + row;
            float4 vb = make_float4(0.f, 0.f, 0.f, 0.f);
            if (nrow < Vv)
                vb = *(const float4*)&W[(size_t)nrow * 512 + ck + k4];
            uint4 ub = make_uint4(f2tf32(vb.x), f2tf32(vb.y), f2tf32(vb.z), f2tf32(vb.w));
            *(uint4*)&Ws[row * VSTRIDE + k4] = ub;
        }
        __syncthreads();

#pragma unroll
        for (int k8 = 0; k8 < 4; k8++) {
            int kk = k8 * 8;
            uint32_t af[4][4];
#pragma unroll
            for (int t = 0; t < 4; t++) {
                int r0 = wm + t * 16 + grp;
                af[t][0] = __float_as_uint(As[r0 * VSTRIDE + kk + qid]);
                af[t][1] = __float_as_uint(As[(r0 + 8) * VSTRIDE + kk + qid]);
                af[t][2] = __float_as_uint(As[r0 * VSTRIDE + kk + qid + 4]);
                af[t][3] = __float_as_uint(As[(r0 + 8) * VSTRIDE + kk + qid + 4]);
            }
            uint32_t bf[4][2];
#pragma unroll
            for (int t = 0; t < 4; t++) {
                int n0 = wn + t * 8 + grp;
                bf[t][0] = __float_as_uint(Ws[n0 * VSTRIDE + kk + qid]);
                bf[t][1] = __float_as_uint(Ws[n0 * VSTRIDE + kk + qid + 4]);
            }
#pragma unroll
            for (int i = 0; i < 4; i++)
#pragma unroll
                for (int j = 0; j < 4; j++) {
                    asm volatile(
                        "mma.sync.aligned.m16n8k8.row.col.f32.tf32.tf32.f32 "
                        "{%0,%1,%2,%3}, {%4,%5,%6,%7}, {%8,%9}, {%0,%1,%2,%3};"
                        : "+f"(acc[i][j][0]), "+f"(acc[i][j][1]),
                          "+f"(acc[i][j][2]), "+f"(acc[i][j][3])
                        : "r"(af[i][0]), "r"(af[i][1]), "r"(af[i][2]), "r"(af[i][3]),
                          "r"(bf[j][0]), "r"(bf[j][1]));
                }
        }
        __syncthreads();
    }

    // Epilogue: fused bias, vectorized float2 stores (n even, Vv even -> pair safe)
#pragma unroll
    for (int i = 0; i < 4; i++) {
        int m0 = wm + i * 16 + grp;
#pragma unroll
        for (int j = 0; j < 4; j++) {
            int n = bn0 + wn + j * 8 + 2 * qid;
            if (n < Vv) {
                float2 b2 = *(const float2*)&bias[n];
                float2 v0 = make_float2(acc[i][j][0] + b2.x, acc[i][j][1] + b2.y);
                float2 v1 = make_float2(acc[i][j][2] + b2.x, acc[i][j][3] + b2.y);
                *(float2*)&Cl[(size_t)m0 * Vv + n] = v0;
                *(float2*)&Cl[(size_t)(m0 + 8) * Vv + n] = v1;
            }
        }
    }
}

// ---------------------------------------------------------------------------
// LSTM elementwise
// ---------------------------------------------------------------------------
__global__ void lstm_kernel(const float* __restrict__ gates, const float* __restrict__ c0,
                            float* __restrict__ out) {
    int idx = blockIdx.x * blockDim.x + threadIdx.x;
    if (idx >= Bb * Hh) return;
    int b = idx >> 9;
    int h = idx & 511;
    const float* g = gates + (size_t)b * 4 * Hh;
    float gi = g[h], gf = g[512 + h], gg = g[1024 + h], go = g[1536 + h];
    float c = sigmoid_fast(gf) * c0[idx] + sigmoid_fast(gi) * tanhf(gg);
    float hh = sigmoid_fast(go) * tanhf(c);
    out[OFF_H + idx] = hh;
    out[OFF_C + idx] = c;
}

// ---------------------------------------------------------------------------
// Attention scores
// ---------------------------------------------------------------------------
__global__ __launch_bounds__(256) void scores_kernel(
    const float* __restrict__ ef, const float* __restrict__ dec,
    const float* __restrict__ vw, const float* __restrict__ Wc,
    const float* __restrict__ cov, float* __restrict__ scores)
{
    __shared__ __align__(16) float s_dec[H2];
    __shared__ __align__(16) float s_v[H2];
    __shared__ __align__(16) float s_wc[H2];
    int b = blockIdx.y;
    int tid = threadIdx.x;
    for (int i = tid; i < H2; i += 256) {
        s_dec[i] = dec[(size_t)b * H2 + i];
        s_v[i] = vw[i];
        s_wc[i] = Wc[i];
    }
    __syncthreads();

    int warp = tid >> 5, lane = tid & 31;
    int t = blockIdx.x * 8 + warp;
    float cv = cov[(size_t)b * Tt + t];
    const float* p = ef + ((size_t)b * Tt + t) * H2;

    float acc = 0.0f;
#pragma unroll
    for (int i = 0; i < 8; i++) {
        int n = i * 128 + lane * 4;
        float4 e4 = *(const float4*)(p + n);
        acc += tanh_fast(e4.x + s_dec[n]     + cv * s_wc[n])     * s_v[n];
        acc += tanh_fast(e4.y + s_dec[n + 1] + cv * s_wc[n + 1]) * s_v[n + 1];
        acc += tanh_fast(e4.z + s_dec[n + 2] + cv * s_wc[n + 2]) * s_v[n + 2];
        acc += tanh_fast(e4.w + s_dec[n + 3] + cv * s_wc[n + 3]) * s_v[n + 3];
    }
#pragma unroll
    for (int o = 16; o > 0; o >>= 1) acc += __shfl_down_sync(0xffffffffu, acc, o);
    if (lane == 0) scores[(size_t)b * Tt + t] = acc;
}

// ---------------------------------------------------------------------------
// Softmax over T + mask renorm + coverage
// ---------------------------------------------------------------------------
__global__ void softmaxT_kernel(const float* __restrict__ scores, const float* __restrict__ mask,
                                const float* __restrict__ cov, float* __restrict__ out)
{
    __shared__ float sm[256];
    int b = blockIdx.x, tid = threadIdx.x;
    int t0 = tid, t1 = tid + 256;
    float s0 = (t0 < Tt) ? scores[(size_t)b * Tt + t0] : -1e30f;
    float s1 = (t1 < Tt) ? scores[(size_t)b * Tt + t1] : -1e30f;

    sm[tid] = fmaxf(s0, s1); __syncthreads();
    for (int s = 128; s > 0; s >>= 1) { if (tid < s) sm[tid] = fmaxf(sm[tid], sm[tid + s]); __syncthreads(); }
    float m = sm[0]; __syncthreads();

    float e0 = (t0 < Tt) ? __expf(s0 - m) : 0.f;
    float e1 = (t1 < Tt) ? __expf(s1 - m) : 0.f;
    sm[tid] = e0 + e1; __syncthreads();
    for (int s = 128; s > 0; s >>= 1) { if (tid < s) sm[tid] += sm[tid + s]; __syncthreads(); }
    float S = sm[0]; __syncthreads();

    float a0 = (t0 < Tt) ? (e0 / S) * mask[(size_t)b * Tt + t0] : 0.f;
    float a1 = (t1 < Tt) ? (e1 / S) * mask[(size_t)b * Tt + t1] : 0.f;
    sm[tid] = a0 + a1; __syncthreads();
    for (int s = 128; s > 0; s >>= 1) { if (tid < s) sm[tid] += sm[tid + s]; __syncthreads(); }
    float S2 = sm[0] + 1e-12f;

    if (t0 < Tt) {
        float a = a0 / S2;
        out[OFF_ATTN + (size_t)b * Tt + t0] = a;
        out[OFF_COV  + (size_t)b * Tt + t0] = cov[(size_t)b * Tt + t0] + a;
    }
    if (t1 < Tt) {
        float a = a1 / S2;
        out[OFF_ATTN + (size_t)b * Tt + t1] = a;
        out[OFF_COV  + (size_t)b * Tt + t1] = cov[(size_t)b * Tt + t1] + a;
    }
}

// ---------------------------------------------------------------------------
// c_t = attn @ encoder_outputs
// ---------------------------------------------------------------------------
__global__ __launch_bounds__(512) void ct_kernel(const float* __restrict__ eo,
                                                 const float* __restrict__ out_ro,
                                                 float* __restrict__ out)
{
    __shared__ float sa[Tt];
    int b = blockIdx.y;
    int n = blockIdx.x * 512 + threadIdx.x;
    if (threadIdx.x < Tt) sa[threadIdx.x] = out_ro[OFF_ATTN + (size_t)b * Tt + threadIdx.x];
    __syncthreads();
    const float* p = eo + (size_t)b * Tt * H2 + n;
    float acc = 0.0f;
#pragma unroll 4
    for (int t = 0; t < Tt; t++) acc += sa[t] * p[(size_t)t * H2];
    out[OFF_CT + (size_t)b * H2 + n] = acc;
}

// ---------------------------------------------------------------------------
// p_gen
// ---------------------------------------------------------------------------
__global__ void pgen_kernel(const float* __restrict__ out_ro, const float* __restrict__ x,
                            const float* __restrict__ Wpg, const float* __restrict__ bpg,
                            float* __restrict__ out)
{
    __shared__ float sm[256];
    int b = blockIdx.x, tid = threadIdx.x;
    const float* ct = out_ro + OFF_CT + (size_t)b * H2;
    const float* h  = out_ro + OFF_H  + (size_t)b * Hh;
    const float* c  = out_ro + OFF_C  + (size_t)b * Hh;
    float acc = 0.0f;
    for (int k = tid; k < H2; k += 256) acc += ct[k] * Wpg[k];
    for (int k = tid; k < Hh; k += 256) acc += h[k] * Wpg[1024 + k] + c[k] * Wpg[1536 + k];
    if (tid < Ee) acc += x[(size_t)b * Ee + tid] * Wpg[2048 + tid];
    sm[tid] = acc; __syncthreads();
    for (int s = 128; s > 0; s >>= 1) { if (tid < s) sm[tid] += sm[tid + s]; __syncthreads(); }
    if (tid == 0) out[OFF_PGEN + b] = sigmoid_fast(sm[0] + bpg[0]);
}

// ---------------------------------------------------------------------------
// Vocab softmax scaled by p_gen -> final_dist
// ---------------------------------------------------------------------------
__global__ __launch_bounds__(1024) void vsoftmax_kernel(const float* __restrict__ logits,
                                                        float* __restrict__ out)
{
    __shared__ float sm[1024];
    int b = blockIdx.x, tid = threadIdx.x;
    const float* L = logits + (size_t)b * Vv;
    float m = -1e30f;
    for (int j = tid; j < Vv; j += 1024) m = fmaxf(m, L[j]);
    sm[tid] = m; __syncthreads();
    for (int s = 512; s > 0; s >>= 1) { if (tid < s) sm[tid] = fmaxf(sm[tid], sm[tid + s]); __syncthreads(); }
    m = sm[0]; __syncthreads();

    float s = 0.0f;
    for (int j = tid; j < Vv; j += 1024) s += __expf(L[j] - m);
    sm[tid] = s; __syncthreads();
    for (int st = 512; st > 0; st >>= 1) { if (tid < st) sm[tid] += sm[tid + st]; __syncthreads(); }
    float S = sm[0];

    float scale = out[OFF_PGEN + b] / S;
    float* F = out + (size_t)b * Vv;
    for (int j = tid; j < Vv; j += 1024) F[j] = __expf(L[j] - m) * scale;
}

// ---------------------------------------------------------------------------
// Pointer scatter
// ---------------------------------------------------------------------------
__global__ void scatter_kernel(const int* __restrict__ ebev, float* __restrict__ out)
{
    int i = blockIdx.x * 256 + threadIdx.x;
    if (i >= Bb * Tt) return;
    int b = i / Tt;
    float pg = out[OFF_PGEN + b];
    float a = out[OFF_ATTN + i];
    atomicAdd(&out[(size_t)b * Vv + ebev[i]], (1.0f - pg) * a);
}

// ---------------------------------------------------------------------------
// Host launch
// ---------------------------------------------------------------------------
static void launch_gemm(const float* A1, int lda1, int K1, const float* W1, int ldw1,
                        const float* A2, int lda2, int K2, const float* W2, int ldw2,
                        const float* b1, const float* b2, float* C, int N, int ksplit)
{
    int steps = (K1 + K2) >> 4;
    int kchunk = (steps + ksplit - 1) / ksplit;
    int ky = (steps + kchunk - 1) / kchunk;
    dim3 grid((N + BN - 1) / BN, ky);
    gemm_bt<<<grid, 256>>>(A1, lda1, K1, W1, ldw1, A2, lda2, K2, W2, ldw2,
                           b1, b2, C, N, kchunk, (ky > 1) ? 1 : 0);
}

extern "C" void kernel_launch(void* const* d_in, const int* in_sizes, int n_in,
                              void* d_out_v, int out_size)
{
    (void)in_sizes; (void)n_in; (void)out_size;
    const int*   y    = (const int*)  d_in[0];
    const float* h0   = (const float*)d_in[1];
    const float* c0   = (const float*)d_in[2];
    const float* ct1  = (const float*)d_in[3];
    const float* eo   = (const float*)d_in[4];
    const float* ef   = (const float*)d_in[5];
    const float* mask = (const float*)d_in[6];
    const int*   ebev = (const int*)  d_in[7];
    const float* cov  = (const float*)d_in[8];
    const float* emb  = (const float*)d_in[9];
    const float* W_c  = (const float*)d_in[10];
    const float* W_dp = (const float*)d_in[11];
    const float* b_dp = (const float*)d_in[12];
    const float* v_w  = (const float*)d_in[13];
    const float* W_xc = (const float*)d_in[14];
    const float* b_xc = (const float*)d_in[15];
    const float* W_ih = (const float*)d_in[16];
    const float* W_hh = (const float*)d_in[17];
    const float* b_ih = (const float*)d_in[18];
    const float* b_hh = (const float*)d_in[19];
    const float* W_pg = (const float*)d_in[20];
    const float* b_pg = (const float*)d_in[21];
    const float* W_o1 = (const float*)d_in[22];
    const float* b_o1 = (const float*)d_in[23];
    const float* W_o2 = (const float*)d_in[24];
    const float* b_o2 = (const float*)d_in[25];
    float* out = (float*)d_out_v;

    float *p_yemb, *p_x, *p_gates, *p_dec, *p_scores, *p_o1, *p_logits;
    cudaGetSymbolAddress((void**)&p_yemb,   g_yemb);
    cudaGetSymbolAddress((void**)&p_x,      g_x);
    cudaGetSymbolAddress((void**)&p_gates,  g_gates);
    cudaGetSymbolAddress((void**)&p_dec,    g_decfea);
    cudaGetSymbolAddress((void**)&p_scores, g_scores);
    cudaGetSymbolAddress((void**)&p_o1,     g_o1);
    cudaGetSymbolAddress((void**)&p_logits, g_logits);

    // 1. embedding gather
    embed_kernel<<<(Bb * Ee + 255) / 256, 256>>>(y, emb, p_yemb);

    // 2. x = [c_t_1 | y_emb] @ W_xc^T + b_xc
    cudaMemsetAsync(p_x, 0, sizeof(float) * Bb * Ee, 0);
    launch_gemm(ct1, H2, H2, W_xc, 1152,
                p_yemb, Ee, Ee, W_xc + 1024, 1152,
                b_xc, nullptr, p_x, Ee, 36);

    // 3. gates = x @ W_ih^T + h0 @ W_hh^T + b_ih + b_hh
    cudaMemsetAsync(p_gates, 0, sizeof(float) * Bb * 4 * Hh, 0);
    launch_gemm(p_x, Ee, Ee, W_ih, Ee,
                h0, Hh, Hh, W_hh, Hh,
                b_ih, b_hh, p_gates, 4 * Hh, 8);

    // 4. LSTM cell
    lstm_kernel<<<(Bb * Hh + 255) / 256, 256>>>(p_gates, c0, out);

    // 5. dec_fea = [h | c] @ W_dp^T + b_dp
    cudaMemsetAsync(p_dec, 0, sizeof(float) * Bb * H2, 0);
    launch_gemm(out + OFF_H, Hh, Hh, W_dp, H2,
                out + OFF_C, Hh, Hh, W_dp + 512, H2,
                b_dp, nullptr, p_dec, H2, 8);

    // 6. attention scores
    scores_kernel<<<dim3(Tt / 8, Bb), 256>>>(ef, p_dec, v_w, W_c, cov, p_scores);

    // 7. softmax over T + mask + coverage
    softmaxT_kernel<<<Bb, 256>>>(p_scores, mask, cov, out);

    // 8. c_t
    ct_kernel<<<dim3(2, Bb), 512>>>(eo, out, out);

    // 9. p_gen
    pgen_kernel<<<Bb, 256>>>(out, p_x, W_pg, b_pg, out);

    // 10. o1 = [h | c_t] @ W_o1^T + b_o1
    cudaMemsetAsync(p_o1, 0, sizeof(float) * Bb * Hh, 0);
    launch_gemm(out + OFF_H, Hh, Hh, W_o1, 3 * Hh,
                out + OFF_CT, H2, H2, W_o1 + 512, 3 * Hh,
                b_o1, nullptr, p_o1, Hh, 16);

    // 11. logits via warp-MMA tf32 GEMM (391 CTAs of N=128)
    vocab_gemm_mma<<<(Vv + 127) / 128, 256>>>(p_o1, W_o2, b_o2, p_logits);

    // 12. vocab softmax
    vsoftmax_kernel<<<Bb, 1024>>>(p_logits, out);

    // 13. pointer scatter
    scatter_kernel<<<(Bb * Tt + 255) / 256, 256>>>(ebev, out);
}

// round 4
// speedup vs baseline: 1.5789x; 1.2188x over previous
#include <cuda_runtime.h>
#include <math.h>
#include <stdint.h>

// Problem constants
#define Bb 128
#define Tt 400
#define Hh 512
#define H2 1024
#define Ee 128
#define Vv 50000

// Output layout (concatenated reference tuple, row-major each)
#define OFF_FINAL 0L
#define OFF_H     6400000L
#define OFF_C     6465536L
#define OFF_CT    6531072L
#define OFF_ATTN  6662144L
#define OFF_PGEN  6713344L
#define OFF_COV   6713472L

// Scratch (device globals: allowed; no runtime allocation)
__device__ float g_yemb[Bb * Ee];
__device__ float g_x[Bb * Ee];
__device__ float g_gates[Bb * 4 * Hh];
__device__ float g_decfea[Bb * H2];
__device__ float g_scores[Bb * Tt];
__device__ float g_o1[Bb * Hh];
__device__ float g_logits[(size_t)Bb * Vv];

__device__ __forceinline__ float tanh_fast(float x) {
    float y;
    asm("tanh.approx.f32 %0, %1;" : "=f"(y) : "f"(x));
    return y;
}
__device__ __forceinline__ float sigmoid_fast(float x) {
    return 1.0f / (1.0f + __expf(-x));
}

// ---------------------------------------------------------------------------
// Embedding gather
// ---------------------------------------------------------------------------
__global__ void embed_kernel(const int* __restrict__ y, const float* __restrict__ emb,
                             float* __restrict__ out) {
    int i = blockIdx.x * blockDim.x + threadIdx.x;
    if (i >= Bb * Ee) return;
    int b = i >> 7;
    int e = i & 127;
    out[i] = emb[(size_t)y[b] * Ee + e];
}

// ---------------------------------------------------------------------------
// Generic small GEMM (FFMA): C[128,N] (+)= A1@W1^T + A2@W2^T + bias, K-split
// ---------------------------------------------------------------------------
#define BM 128
#define BN 64
#define BK 16

__global__ __launch_bounds__(256) void gemm_bt(
    const float* __restrict__ A1, int lda1, int K1,
    const float* __restrict__ W1, int ldw1,
    const float* __restrict__ A2, int lda2, int K2,
    const float* __restrict__ W2, int ldw2,
    const float* __restrict__ bias1, const float* __restrict__ bias2,
    float* __restrict__ C, int N, int kchunk, int split)
{
    __shared__ __align__(16) float As[BK][BM + 4];
    __shared__ __align__(16) float Ws[BK][BN + 4];

    int tid = threadIdx.x;
    int tx = tid & 15;
    int ty = tid >> 4;
    int bn0 = blockIdx.x * BN;

    int steps_total = (K1 + K2) >> 4;
    int s0 = blockIdx.y * kchunk;
    int s1 = min(s0 + kchunk, steps_total);
    if (s0 >= steps_total) return;

    float acc[8][4];
#pragma unroll
    for (int i = 0; i < 8; i++)
#pragma unroll
        for (int j = 0; j < 4; j++) acc[i][j] = 0.0f;

    int a_row = tid >> 2;
    int a_c4 = (tid & 3) * 4;

    for (int s = s0; s < s1; ++s) {
        int kk = s << 4;
        const float* Ap; int lda; int ko;
        const float* Wp; int ldw;
        if (kk < K1) { Ap = A1; lda = lda1; ko = kk;      Wp = W1; ldw = ldw1; }
        else         { Ap = A2; lda = lda2; ko = kk - K1; Wp = W2; ldw = ldw2; }

        {
            float4 v = *(const float4*)&Ap[(size_t)a_row * lda + ko + a_c4];
            As[a_c4 + 0][a_row] = v.x; As[a_c4 + 1][a_row] = v.y;
            As[a_c4 + 2][a_row] = v.z; As[a_c4 + 3][a_row] = v.w;
            int r2 = a_row + 64;
            float4 v2 = *(const float4*)&Ap[(size_t)r2 * lda + ko + a_c4];
            As[a_c4 + 0][r2] = v2.x; As[a_c4 + 1][r2] = v2.y;
            As[a_c4 + 2][r2] = v2.z; As[a_c4 + 3][r2] = v2.w;
        }
        {
            int n = a_row;
            float4 v = make_float4(0.f, 0.f, 0.f, 0.f);
            if (bn0 + n < N)
                v = *(const float4*)&Wp[(size_t)(bn0 + n) * ldw + ko + a_c4];
            Ws[a_c4 + 0][n] = v.x; Ws[a_c4 + 1][n] = v.y;
            Ws[a_c4 + 2][n] = v.z; Ws[a_c4 + 3][n] = v.w;
        }
        __syncthreads();

#pragma unroll
        for (int k = 0; k < BK; k++) {
            float4 a0 = *(const float4*)&As[k][ty * 8];
            float4 a1 = *(const float4*)&As[k][ty * 8 + 4];
            float4 w  = *(const float4*)&Ws[k][tx * 4];
            float am[8] = {a0.x, a0.y, a0.z, a0.w, a1.x, a1.y, a1.z, a1.w};
            float wn[4] = {w.x, w.y, w.z, w.w};
#pragma unroll
            for (int i = 0; i < 8; i++)
#pragma unroll
                for (int j = 0; j < 4; j++) acc[i][j] += am[i] * wn[j];
        }
        __syncthreads();
    }

    bool addb = (blockIdx.y == 0);
#pragma unroll
    for (int i = 0; i < 8; i++) {
        int m = ty * 8 + i;
#pragma unroll
        for (int j = 0; j < 4; j++) {
            int n = bn0 + tx * 4 + j;
            if (n < N) {
                float v = acc[i][j];
                if (addb) {
                    if (bias1) v += bias1[n];
                    if (bias2) v += bias2[n];
                }
                if (split) atomicAdd(&C[(size_t)m * N + n], v);
                else       C[(size_t)m * N + n] = v;
            }
        }
    }
}

// ---------------------------------------------------------------------------
// Vocab GEMM via warp-level tf32 MMA + cp.async 2-stage pipeline:
// logits[128, 50000] = o1[128,512] @ W_o2[50000,512]^T + b_o2
// CTA tile: M=128, N=128, K=512 in 32 chunks of BK=16.
// 8 warps (2 M x 4 N), warp tile m64 n32, mma.m16n8k8.tf32 (raw fp32 bits),
// fp32 accumulate, fused bias epilogue.
// ---------------------------------------------------------------------------
#define VG_LDS 20                       // smem row stride in floats
#define VG_STAGEF (128 * VG_LDS)        // floats per stage per tile
#define VG_STAGEB (VG_STAGEF * 4)       // bytes per stage per tile

__device__ __forceinline__ uint32_t smem_u32(const void* p) {
    return (uint32_t)__cvta_generic_to_shared(p);
}

__device__ __forceinline__ void vg_prefetch(
    int s, int stage, const float* __restrict__ A, const float* __restrict__ W,
    int bn0, uint32_t sA, uint32_t sW)
{
    int ck = s * 16;
    int tid = threadIdx.x;
#pragma unroll
    for (int i = 0; i < 2; i++) {
        int slot = i * 256 + tid;       // 0..511
        int row = slot >> 2;            // 0..127
        int c4 = (slot & 3) << 2;       // 0,4,8,12
        uint32_t soff = (uint32_t)(stage * VG_STAGEB + (row * VG_LDS + c4) * 4);
        asm volatile("cp.async.cg.shared.global [%0], [%1], 16;"
                     :: "r"(sA + soff), "l"(A + row * 512 + ck + c4) : "memory");
        int nrow = bn0 + row;
        if (nrow < Vv)
            asm volatile("cp.async.cg.shared.global [%0], [%1], 16;"
                         :: "r"(sW + soff), "l"(W + (size_t)nrow * 512 + ck + c4) : "memory");
    }
    asm volatile("cp.async.commit_group;" ::: "memory");
}

__global__ __launch_bounds__(256) void vocab_gemm_mma(
    const float* __restrict__ A,      // [128,512]
    const float* __restrict__ W,      // [50000,512]
    const float* __restrict__ bias,   // [50000]
    float* __restrict__ Cl)           // [128,50000]
{
    __shared__ __align__(16) float As[2 * VG_STAGEF];
    __shared__ __align__(16) float Ws[2 * VG_STAGEF];

    int tid = threadIdx.x;
    int lane = tid & 31;
    int wid = tid >> 5;
    int wm = (wid & 1) * 64;     // warp M offset
    int wn = (wid >> 1) * 32;    // warp N offset
    int bn0 = blockIdx.x * 128;

    int grp = lane >> 2;         // 0..7
    int qid = lane & 3;          // 0..3

    uint32_t sA = smem_u32(As);
    uint32_t sW = smem_u32(Ws);

    // Zero-fill W smem rows that are out of range (last CTA only), both stages.
    if (bn0 + 128 > Vv) {
        for (int slot = tid; slot < 512; slot += 256) {
            int row = slot >> 2;
            int c4 = (slot & 3) << 2;
            if (bn0 + row >= Vv) {
                *(float4*)&Ws[row * VG_LDS + c4] = make_float4(0.f, 0.f, 0.f, 0.f);
                *(float4*)&Ws[VG_STAGEF + row * VG_LDS + c4] = make_float4(0.f, 0.f, 0.f, 0.f);
            }
        }
    }

    float acc[4][4][4];
#pragma unroll
    for (int i = 0; i < 4; i++)
#pragma unroll
        for (int j = 0; j < 4; j++)
#pragma unroll
            for (int r = 0; r < 4; r++) acc[i][j][r] = 0.0f;

    vg_prefetch(0, 0, A, W, bn0, sA, sW);

    for (int s = 0; s < 32; s++) {
        int stage = s & 1;
        if (s + 1 < 32) {
            vg_prefetch(s + 1, stage ^ 1, A, W, bn0, sA, sW);
            asm volatile("cp.async.wait_group 1;" ::: "memory");
        } else {
            asm volatile("cp.async.wait_group 0;" ::: "memory");
        }
        __syncthreads();

        const float* as = As + stage * VG_STAGEF;
        const float* ws = Ws + stage * VG_STAGEF;

#pragma unroll
        for (int k8 = 0; k8 < 2; k8++) {
            int kk = k8 * 8;
            uint32_t af[4][4];
#pragma unroll
            for (int t = 0; t < 4; t++) {
                int r0 = wm + t * 16 + grp;
                af[t][0] = __float_as_uint(as[r0 * VG_LDS + kk + qid]);
                af[t][1] = __float_as_uint(as[(r0 + 8) * VG_LDS + kk + qid]);
                af[t][2] = __float_as_uint(as[r0 * VG_LDS + kk + qid + 4]);
                af[t][3] = __float_as_uint(as[(r0 + 8) * VG_LDS + kk + qid + 4]);
            }
            uint32_t bf[4][2];
#pragma unroll
            for (int t = 0; t < 4; t++) {
                int n0 = wn + t * 8 + grp;
                bf[t][0] = __float_as_uint(ws[n0 * VG_LDS + kk + qid]);
                bf[t][1] = __float_as_uint(ws[n0 * VG_LDS + kk + qid + 4]);
            }
#pragma unroll
            for (int i = 0; i < 4; i++)
#pragma unroll
                for (int j = 0; j < 4; j++) {
                    asm volatile(
                        "mma.sync.aligned.m16n8k8.row.col.f32.tf32.tf32.f32 "
                        "{%0,%1,%2,%3}, {%4,%5,%6,%7}, {%8,%9}, {%0,%1,%2,%3};"
                        : "+f"(acc[i][j][0]), "+f"(acc[i][j][1]),
                          "+f"(acc[i][j][2]), "+f"(acc[i][j][3])
                        : "r"(af[i][0]), "r"(af[i][1]), "r"(af[i][2]), "r"(af[i][3]),
                          "r"(bf[j][0]), "r"(bf[j][1]));
                }
        }
        __syncthreads();
    }

    // Epilogue: fused bias, vectorized float2 stores
#pragma unroll
    for (int i = 0; i < 4; i++) {
        int m0 = wm + i * 16 + grp;
#pragma unroll
        for (int j = 0; j < 4; j++) {
            int n = bn0 + wn + j * 8 + 2 * qid;
            if (n < Vv) {
                float2 b2 = *(const float2*)&bias[n];
                float2 v0 = make_float2(acc[i][j][0] + b2.x, acc[i][j][1] + b2.y);
                float2 v1 = make_float2(acc[i][j][2] + b2.x, acc[i][j][3] + b2.y);
                *(float2*)&Cl[(size_t)m0 * Vv + n] = v0;
                *(float2*)&Cl[(size_t)(m0 + 8) * Vv + n] = v1;
            }
        }
    }
}

// ---------------------------------------------------------------------------
// LSTM elementwise
// ---------------------------------------------------------------------------
__global__ void lstm_kernel(const float* __restrict__ gates, const float* __restrict__ c0,
                            float* __restrict__ out) {
    int idx = blockIdx.x * blockDim.x + threadIdx.x;
    if (idx >= Bb * Hh) return;
    int b = idx >> 9;
    int h = idx & 511;
    const float* g = gates + (size_t)b * 4 * Hh;
    float gi = g[h], gf = g[512 + h], gg = g[1024 + h], go = g[1536 + h];
    float c = sigmoid_fast(gf) * c0[idx] + sigmoid_fast(gi) * tanhf(gg);
    float hh = sigmoid_fast(go) * tanhf(c);
    out[OFF_H + idx] = hh;
    out[OFF_C + idx] = c;
}

// ---------------------------------------------------------------------------
// Attention scores
// ---------------------------------------------------------------------------
__global__ __launch_bounds__(256) void scores_kernel(
    const float* __restrict__ ef, const float* __restrict__ dec,
    const float* __restrict__ vw, const float* __restrict__ Wc,
    const float* __restrict__ cov, float* __restrict__ scores)
{
    __shared__ __align__(16) float s_dec[H2];
    __shared__ __align__(16) float s_v[H2];
    __shared__ __align__(16) float s_wc[H2];
    int b = blockIdx.y;
    int tid = threadIdx.x;
    for (int i = tid; i < H2; i += 256) {
        s_dec[i] = dec[(size_t)b * H2 + i];
        s_v[i] = vw[i];
        s_wc[i] = Wc[i];
    }
    __syncthreads();

    int warp = tid >> 5, lane = tid & 31;
    int t = blockIdx.x * 8 + warp;
    float cv = cov[(size_t)b * Tt + t];
    const float* p = ef + ((size_t)b * Tt + t) * H2;

    float acc = 0.0f;
#pragma unroll
    for (int i = 0; i < 8; i++) {
        int n = i * 128 + lane * 4;
        float4 e4 = *(const float4*)(p + n);
        acc += tanh_fast(e4.x + s_dec[n]     + cv * s_wc[n])     * s_v[n];
        acc += tanh_fast(e4.y + s_dec[n + 1] + cv * s_wc[n + 1]) * s_v[n + 1];
        acc += tanh_fast(e4.z + s_dec[n + 2] + cv * s_wc[n + 2]) * s_v[n + 2];
        acc += tanh_fast(e4.w + s_dec[n + 3] + cv * s_wc[n + 3]) * s_v[n + 3];
    }
#pragma unroll
    for (int o = 16; o > 0; o >>= 1) acc += __shfl_down_sync(0xffffffffu, acc, o);
    if (lane == 0) scores[(size_t)b * Tt + t] = acc;
}

// ---------------------------------------------------------------------------
// Softmax over T + mask renorm + coverage
// ---------------------------------------------------------------------------
__global__ void softmaxT_kernel(const float* __restrict__ scores, const float* __restrict__ mask,
                                const float* __restrict__ cov, float* __restrict__ out)
{
    __shared__ float sm[256];
    int b = blockIdx.x, tid = threadIdx.x;
    int t0 = tid, t1 = tid + 256;
    float s0 = (t0 < Tt) ? scores[(size_t)b * Tt + t0] : -1e30f;
    float s1 = (t1 < Tt) ? scores[(size_t)b * Tt + t1] : -1e30f;

    sm[tid] = fmaxf(s0, s1); __syncthreads();
    for (int s = 128; s > 0; s >>= 1) { if (tid < s) sm[tid] = fmaxf(sm[tid], sm[tid + s]); __syncthreads(); }
    float m = sm[0]; __syncthreads();

    float e0 = (t0 < Tt) ? __expf(s0 - m) : 0.f;
    float e1 = (t1 < Tt) ? __expf(s1 - m) : 0.f;
    sm[tid] = e0 + e1; __syncthreads();
    for (int s = 128; s > 0; s >>= 1) { if (tid < s) sm[tid] += sm[tid + s]; __syncthreads(); }
    float S = sm[0]; __syncthreads();

    float a0 = (t0 < Tt) ? (e0 / S) * mask[(size_t)b * Tt + t0] : 0.f;
    float a1 = (t1 < Tt) ? (e1 / S) * mask[(size_t)b * Tt + t1] : 0.f;
    sm[tid] = a0 + a1; __syncthreads();
    for (int s = 128; s > 0; s >>= 1) { if (tid < s) sm[tid] += sm[tid + s]; __syncthreads(); }
    float S2 = sm[0] + 1e-12f;

    if (t0 < Tt) {
        float a = a0 / S2;
        out[OFF_ATTN + (size_t)b * Tt + t0] = a;
        out[OFF_COV  + (size_t)b * Tt + t0] = cov[(size_t)b * Tt + t0] + a;
    }
    if (t1 < Tt) {
        float a = a1 / S2;
        out[OFF_ATTN + (size_t)b * Tt + t1] = a;
        out[OFF_COV  + (size_t)b * Tt + t1] = cov[(size_t)b * Tt + t1] + a;
    }
}

// ---------------------------------------------------------------------------
// c_t = attn @ encoder_outputs
// ---------------------------------------------------------------------------
__global__ __launch_bounds__(512) void ct_kernel(const float* __restrict__ eo,
                                                 const float* __restrict__ out_ro,
                                                 float* __restrict__ out)
{
    __shared__ float sa[Tt];
    int b = blockIdx.y;
    int n = blockIdx.x * 512 + threadIdx.x;
    if (threadIdx.x < Tt) sa[threadIdx.x] = out_ro[OFF_ATTN + (size_t)b * Tt + threadIdx.x];
    __syncthreads();
    const float* p = eo + (size_t)b * Tt * H2 + n;
    float acc = 0.0f;
#pragma unroll 8
    for (int t = 0; t < Tt; t++) acc += sa[t] * p[(size_t)t * H2];
    out[OFF_CT + (size_t)b * H2 + n] = acc;
}

// ---------------------------------------------------------------------------
// p_gen
// ---------------------------------------------------------------------------
__global__ void pgen_kernel(const float* __restrict__ out_ro, const float* __restrict__ x,
                            const float* __restrict__ Wpg, const float* __restrict__ bpg,
                            float* __restrict__ out)
{
    __shared__ float sm[256];
    int b = blockIdx.x, tid = threadIdx.x;
    const float* ct = out_ro + OFF_CT + (size_t)b * H2;
    const float* h  = out_ro + OFF_H  + (size_t)b * Hh;
    const float* c  = out_ro + OFF_C  + (size_t)b * Hh;
    float acc = 0.0f;
    for (int k = tid; k < H2; k += 256) acc += ct[k] * Wpg[k];
    for (int k = tid; k < Hh; k += 256) acc += h[k] * Wpg[1024 + k] + c[k] * Wpg[1536 + k];
    if (tid < Ee) acc += x[(size_t)b * Ee + tid] * Wpg[2048 + tid];
    sm[tid] = acc; __syncthreads();
    for (int s = 128; s > 0; s >>= 1) { if (tid < s) sm[tid] += sm[tid + s]; __syncthreads(); }
    if (tid == 0) out[OFF_PGEN + b] = sigmoid_fast(sm[0] + bpg[0]);
}

// ---------------------------------------------------------------------------
// Vocab softmax scaled by p_gen -> final_dist (online max+sum, 2 passes)
// ---------------------------------------------------------------------------
__global__ __launch_bounds__(1024) void vsoftmax_kernel(const float* __restrict__ logits,
                                                        float* __restrict__ out)
{
    __shared__ float smx[1024];
    __shared__ float ssm[1024];
    int b = blockIdx.x, tid = threadIdx.x;
    const float* L = logits + (size_t)b * Vv;

    float m = -1e30f, s = 0.0f;
    for (int j = tid; j < Vv; j += 1024) {
        float v = L[j];
        float nm = fmaxf(m, v);
        s = s * __expf(m - nm) + __expf(v - nm);
        m = nm;
    }
    smx[tid] = m; ssm[tid] = s; __syncthreads();
    for (int st = 512; st > 0; st >>= 1) {
        if (tid < st) {
            float m2 = smx[tid + st], s2 = ssm[tid + st];
            float m1 = smx[tid],      s1 = ssm[tid];
            float nm = fmaxf(m1, m2);
            ssm[tid] = s1 * __expf(m1 - nm) + s2 * __expf(m2 - nm);
            smx[tid] = nm;
        }
        __syncthreads();
    }
    float M = smx[0], S = ssm[0];

    float scale = out[OFF_PGEN + b] / S;
    float* F = out + (size_t)b * Vv;
    for (int j = tid; j < Vv; j += 1024) F[j] = __expf(L[j] - M) * scale;
}

// ---------------------------------------------------------------------------
// Pointer scatter
// ---------------------------------------------------------------------------
__global__ void scatter_kernel(const int* __restrict__ ebev, float* __restrict__ out)
{
    int i = blockIdx.x * 256 + threadIdx.x;
    if (i >= Bb * Tt) return;
    int b = i / Tt;
    float pg = out[OFF_PGEN + b];
    float a = out[OFF_ATTN + i];
    atomicAdd(&out[(size_t)b * Vv + ebev[i]], (1.0f - pg) * a);
}

// ---------------------------------------------------------------------------
// Host launch
// ---------------------------------------------------------------------------
static void launch_gemm(const float* A1, int lda1, int K1, const float* W1, int ldw1,
                        const float* A2, int lda2, int K2, const float* W2, int ldw2,
                        const float* b1, const float* b2, float* C, int N, int ksplit)
{
    int steps = (K1 + K2) >> 4;
    int kchunk = (steps + ksplit - 1) / ksplit;
    int ky = (steps + kchunk - 1) / kchunk;
    dim3 grid((N + BN - 1) / BN, ky);
    gemm_bt<<<grid, 256>>>(A1, lda1, K1, W1, ldw1, A2, lda2, K2, W2, ldw2,
                           b1, b2, C, N, kchunk, (ky > 1) ? 1 : 0);
}

extern "C" void kernel_launch(void* const* d_in, const int* in_sizes, int n_in,
                              void* d_out_v, int out_size)
{
    (void)in_sizes; (void)n_in; (void)out_size;
    const int*   y    = (const int*)  d_in[0];
    const float* h0   = (const float*)d_in[1];
    const float* c0   = (const float*)d_in[2];
    const float* ct1  = (const float*)d_in[3];
    const float* eo   = (const float*)d_in[4];
    const float* ef   = (const float*)d_in[5];
    const float* mask = (const float*)d_in[6];
    const int*   ebev = (const int*)  d_in[7];
    const float* cov  = (const float*)d_in[8];
    const float* emb  = (const float*)d_in[9];
    const float* W_c  = (const float*)d_in[10];
    const float* W_dp = (const float*)d_in[11];
    const float* b_dp = (const float*)d_in[12];
    const float* v_w  = (const float*)d_in[13];
    const float* W_xc = (const float*)d_in[14];
    const float* b_xc = (const float*)d_in[15];
    const float* W_ih = (const float*)d_in[16];
    const float* W_hh = (const float*)d_in[17];
    const float* b_ih = (const float*)d_in[18];
    const float* b_hh = (const float*)d_in[19];
    const float* W_pg = (const float*)d_in[20];
    const float* b_pg = (const float*)d_in[21];
    const float* W_o1 = (const float*)d_in[22];
    const float* b_o1 = (const float*)d_in[23];
    const float* W_o2 = (const float*)d_in[24];
    const float* b_o2 = (const float*)d_in[25];
    float* out = (float*)d_out_v;

    float *p_yemb, *p_x, *p_gates, *p_dec, *p_scores, *p_o1, *p_logits;
    cudaGetSymbolAddress((void**)&p_yemb,   g_yemb);
    cudaGetSymbolAddress((void**)&p_x,      g_x);
    cudaGetSymbolAddress((void**)&p_gates,  g_gates);
    cudaGetSymbolAddress((void**)&p_dec,    g_decfea);
    cudaGetSymbolAddress((void**)&p_scores, g_scores);
    cudaGetSymbolAddress((void**)&p_o1,     g_o1);
    cudaGetSymbolAddress((void**)&p_logits, g_logits);

    // 1. embedding gather
    embed_kernel<<<(Bb * Ee + 255) / 256, 256>>>(y, emb, p_yemb);

    // 2. x = [c_t_1 | y_emb] @ W_xc^T + b_xc
    cudaMemsetAsync(p_x, 0, sizeof(float) * Bb * Ee, 0);
    launch_gemm(ct1, H2, H2, W_xc, 1152,
                p_yemb, Ee, Ee, W_xc + 1024, 1152,
                b_xc, nullptr, p_x, Ee, 36);

    // 3. gates = x @ W_ih^T + h0 @ W_hh^T + b_ih + b_hh
    cudaMemsetAsync(p_gates, 0, sizeof(float) * Bb * 4 * Hh, 0);
    launch_gemm(p_x, Ee, Ee, W_ih, Ee,
                h0, Hh, Hh, W_hh, Hh,
                b_ih, b_hh, p_gates, 4 * Hh, 8);

    // 4. LSTM cell
    lstm_kernel<<<(Bb * Hh + 255) / 256, 256>>>(p_gates, c0, out);

    // 5. dec_fea = [h | c] @ W_dp^T + b_dp
    cudaMemsetAsync(p_dec, 0, sizeof(float) * Bb * H2, 0);
    launch_gemm(out + OFF_H, Hh, Hh, W_dp, H2,
                out + OFF_C, Hh, Hh, W_dp + 512, H2,
                b_dp, nullptr, p_dec, H2, 8);

    // 6. attention scores
    scores_kernel<<<dim3(Tt / 8, Bb), 256>>>(ef, p_dec, v_w, W_c, cov, p_scores);

    // 7. softmax over T + mask + coverage
    softmaxT_kernel<<<Bb, 256>>>(p_scores, mask, cov, out);

    // 8. c_t
    ct_kernel<<<dim3(2, Bb), 512>>>(eo, out, out);

    // 9. p_gen
    pgen_kernel<<<Bb, 256>>>(out, p_x, W_pg, b_pg, out);

    // 10. o1 = [h | c_t] @ W_o1^T + b_o1
    cudaMemsetAsync(p_o1, 0, sizeof(float) * Bb * Hh, 0);
    launch_gemm(out + OFF_H, Hh, Hh, W_o1, 3 * Hh,
                out + OFF_CT, H2, H2, W_o1 + 512, 3 * Hh,
                b_o1, nullptr, p_o1, Hh, 16);

    // 11. logits via warp-MMA tf32 GEMM with cp.async pipeline (391 CTAs)
    vocab_gemm_mma<<<(Vv + 127) / 128, 256>>>(p_o1, W_o2, b_o2, p_logits);

    // 12. vocab softmax (online)
    vsoftmax_kernel<<<Bb, 1024>>>(p_logits, out);

    // 13. pointer scatter
    scatter_kernel<<<(Bb * Tt + 255) / 256, 256>>>(ebev, out);
}

// round 5
// speedup vs baseline: 1.6092x; 1.0192x over previous
#include <cuda_runtime.h>
#include <math.h>
#include <stdint.h>

// Problem constants
#define Bb 128
#define Tt 400
#define Hh 512
#define H2 1024
#define Ee 128
#define Vv 50000

// Output layout (concatenated reference tuple, row-major each)
#define OFF_FINAL 0L
#define OFF_H     6400000L
#define OFF_C     6465536L
#define OFF_CT    6531072L
#define OFF_ATTN  6662144L
#define OFF_PGEN  6713344L
#define OFF_COV   6713472L

// Scratch (device globals: allowed; no runtime allocation)
__device__ float g_yemb[Bb * Ee];
__device__ float g_x[Bb * Ee];
__device__ float g_gates[Bb * 4 * Hh];
__device__ float g_decfea[Bb * H2];
__device__ float g_scores[Bb * Tt];
__device__ float g_o1[Bb * Hh];
__device__ float g_logits[(size_t)Bb * Vv];

__device__ __forceinline__ float tanh_fast(float x) {
    float y;
    asm("tanh.approx.f32 %0, %1;" : "=f"(y) : "f"(x));
    return y;
}
__device__ __forceinline__ float sigmoid_fast(float x) {
    return 1.0f / (1.0f + __expf(-x));
}

// ---------------------------------------------------------------------------
// Embedding gather
// ---------------------------------------------------------------------------
__global__ void embed_kernel(const int* __restrict__ y, const float* __restrict__ emb,
                             float* __restrict__ out) {
    int i = blockIdx.x * blockDim.x + threadIdx.x;
    if (i >= Bb * Ee) return;
    int b = i >> 7;
    int e = i & 127;
    out[i] = emb[(size_t)y[b] * Ee + e];
}

// ---------------------------------------------------------------------------
// Generic small GEMM (FFMA): C[128,N] (+)= A1@W1^T + A2@W2^T + bias, K-split
// ---------------------------------------------------------------------------
#define BM 128
#define BN 64
#define BK 16

__global__ __launch_bounds__(256) void gemm_bt(
    const float* __restrict__ A1, int lda1, int K1,
    const float* __restrict__ W1, int ldw1,
    const float* __restrict__ A2, int lda2, int K2,
    const float* __restrict__ W2, int ldw2,
    const float* __restrict__ bias1, const float* __restrict__ bias2,
    float* __restrict__ C, int N, int kchunk, int split)
{
    __shared__ __align__(16) float As[BK][BM + 4];
    __shared__ __align__(16) float Ws[BK][BN + 4];

    int tid = threadIdx.x;
    int tx = tid & 15;
    int ty = tid >> 4;
    int bn0 = blockIdx.x * BN;

    int steps_total = (K1 + K2) >> 4;
    int s0 = blockIdx.y * kchunk;
    int s1 = min(s0 + kchunk, steps_total);
    if (s0 >= steps_total) return;

    float acc[8][4];
#pragma unroll
    for (int i = 0; i < 8; i++)
#pragma unroll
        for (int j = 0; j < 4; j++) acc[i][j] = 0.0f;

    int a_row = tid >> 2;
    int a_c4 = (tid & 3) * 4;

    for (int s = s0; s < s1; ++s) {
        int kk = s << 4;
        const float* Ap; int lda; int ko;
        const float* Wp; int ldw;
        if (kk < K1) { Ap = A1; lda = lda1; ko = kk;      Wp = W1; ldw = ldw1; }
        else         { Ap = A2; lda = lda2; ko = kk - K1; Wp = W2; ldw = ldw2; }

        {
            float4 v = *(const float4*)&Ap[(size_t)a_row * lda + ko + a_c4];
            As[a_c4 + 0][a_row] = v.x; As[a_c4 + 1][a_row] = v.y;
            As[a_c4 + 2][a_row] = v.z; As[a_c4 + 3][a_row] = v.w;
            int r2 = a_row + 64;
            float4 v2 = *(const float4*)&Ap[(size_t)r2 * lda + ko + a_c4];
            As[a_c4 + 0][r2] = v2.x; As[a_c4 + 1][r2] = v2.y;
            As[a_c4 + 2][r2] = v2.z; As[a_c4 + 3][r2] = v2.w;
        }
        {
            int n = a_row;
            float4 v = make_float4(0.f, 0.f, 0.f, 0.f);
            if (bn0 + n < N)
                v = *(const float4*)&Wp[(size_t)(bn0 + n) * ldw + ko + a_c4];
            Ws[a_c4 + 0][n] = v.x; Ws[a_c4 + 1][n] = v.y;
            Ws[a_c4 + 2][n] = v.z; Ws[a_c4 + 3][n] = v.w;
        }
        __syncthreads();

#pragma unroll
        for (int k = 0; k < BK; k++) {
            float4 a0 = *(const float4*)&As[k][ty * 8];
            float4 a1 = *(const float4*)&As[k][ty * 8 + 4];
            float4 w  = *(const float4*)&Ws[k][tx * 4];
            float am[8] = {a0.x, a0.y, a0.z, a0.w, a1.x, a1.y, a1.z, a1.w};
            float wn[4] = {w.x, w.y, w.z, w.w};
#pragma unroll
            for (int i = 0; i < 8; i++)
#pragma unroll
                for (int j = 0; j < 4; j++) acc[i][j] += am[i] * wn[j];
        }
        __syncthreads();
    }

    bool addb = (blockIdx.y == 0);
#pragma unroll
    for (int i = 0; i < 8; i++) {
        int m = ty * 8 + i;
#pragma unroll
        for (int j = 0; j < 4; j++) {
            int n = bn0 + tx * 4 + j;
            if (n < N) {
                float v = acc[i][j];
                if (addb) {
                    if (bias1) v += bias1[n];
                    if (bias2) v += bias2[n];
                }
                if (split) atomicAdd(&C[(size_t)m * N + n], v);
                else       C[(size_t)m * N + n] = v;
            }
        }
    }
}

// ---------------------------------------------------------------------------
// Vocab GEMM via warp-level tf32 MMA + 4-stage cp.async pipeline:
// logits[128, 50000] = o1[128,512] @ W_o2[50000,512]^T + b_o2
// CTA tile: M=128, N=128, K=512 in 32 chunks of BK=16.
// ---------------------------------------------------------------------------
#define VG_LDS 20                       // smem row stride in floats
#define VG_STAGEF (128 * VG_LDS)        // floats per stage per tile
#define VG_STAGEB (VG_STAGEF * 4)       // bytes per stage per tile
#define VG_STAGES 4
#define VG_SMEM_BYTES (VG_STAGES * VG_STAGEB * 2)

__device__ __forceinline__ uint32_t smem_u32(const void* p) {
    return (uint32_t)__cvta_generic_to_shared(p);
}

__device__ __forceinline__ void vg_prefetch(
    int s, int stage, const float* __restrict__ A, const float* __restrict__ W,
    int bn0, uint32_t sA, uint32_t sW)
{
    int ck = s * 16;
    int tid = threadIdx.x;
#pragma unroll
    for (int i = 0; i < 2; i++) {
        int slot = i * 256 + tid;       // 0..511
        int row = slot >> 2;            // 0..127
        int c4 = (slot & 3) << 2;       // 0,4,8,12
        uint32_t soff = (uint32_t)(stage * VG_STAGEB + (row * VG_LDS + c4) * 4);
        asm volatile("cp.async.cg.shared.global [%0], [%1], 16;"
                     :: "r"(sA + soff), "l"(A + row * 512 + ck + c4) : "memory");
        int nrow = bn0 + row;
        if (nrow < Vv)
            asm volatile("cp.async.cg.shared.global [%0], [%1], 16;"
                         :: "r"(sW + soff), "l"(W + (size_t)nrow * 512 + ck + c4) : "memory");
    }
    asm volatile("cp.async.commit_group;" ::: "memory");
}

__global__ __launch_bounds__(256) void vocab_gemm_mma(
    const float* __restrict__ A,      // [128,512]
    const float* __restrict__ W,      // [50000,512]
    const float* __restrict__ bias,   // [50000]
    float* __restrict__ Cl)           // [128,50000]
{
    extern __shared__ __align__(16) float vgsm[];
    float* As = vgsm;
    float* Ws = vgsm + VG_STAGES * VG_STAGEF;

    int tid = threadIdx.x;
    int lane = tid & 31;
    int wid = tid >> 5;
    int wm = (wid & 1) * 64;     // warp M offset
    int wn = (wid >> 1) * 32;    // warp N offset
    int bn0 = blockIdx.x * 128;

    int grp = lane >> 2;         // 0..7
    int qid = lane & 3;          // 0..3

    uint32_t sA = smem_u32(As);
    uint32_t sW = smem_u32(Ws);

    // Zero-fill W smem rows that are out of range (last CTA only), all stages.
    if (bn0 + 128 > Vv) {
#pragma unroll
        for (int st = 0; st < VG_STAGES; st++)
            for (int slot = tid; slot < 512; slot += 256) {
                int row = slot >> 2;
                int c4 = (slot & 3) << 2;
                if (bn0 + row >= Vv)
                    *(float4*)&Ws[st * VG_STAGEF + row * VG_LDS + c4] =
                        make_float4(0.f, 0.f, 0.f, 0.f);
            }
        __syncthreads();
    }

    float acc[4][4][4];
#pragma unroll
    for (int i = 0; i < 4; i++)
#pragma unroll
        for (int j = 0; j < 4; j++)
#pragma unroll
            for (int r = 0; r < 4; r++) acc[i][j][r] = 0.0f;

    vg_prefetch(0, 0, A, W, bn0, sA, sW);
    vg_prefetch(1, 1, A, W, bn0, sA, sW);
    vg_prefetch(2, 2, A, W, bn0, sA, sW);

    for (int s = 0; s < 32; s++) {
        int stage = s & 3;
        if (s < 29) {
            vg_prefetch(s + 3, (s + 3) & 3, A, W, bn0, sA, sW);
            asm volatile("cp.async.wait_group 3;" ::: "memory");
        } else if (s == 29) {
            asm volatile("cp.async.wait_group 2;" ::: "memory");
        } else if (s == 30) {
            asm volatile("cp.async.wait_group 1;" ::: "memory");
        } else {
            asm volatile("cp.async.wait_group 0;" ::: "memory");
        }
        __syncthreads();

        const float* as = As + stage * VG_STAGEF;
        const float* ws = Ws + stage * VG_STAGEF;

#pragma unroll
        for (int k8 = 0; k8 < 2; k8++) {
            int kk = k8 * 8;
            uint32_t af[4][4];
#pragma unroll
            for (int t = 0; t < 4; t++) {
                int r0 = wm + t * 16 + grp;
                af[t][0] = __float_as_uint(as[r0 * VG_LDS + kk + qid]);
                af[t][1] = __float_as_uint(as[(r0 + 8) * VG_LDS + kk + qid]);
                af[t][2] = __float_as_uint(as[r0 * VG_LDS + kk + qid + 4]);
                af[t][3] = __float_as_uint(as[(r0 + 8) * VG_LDS + kk + qid + 4]);
            }
            uint32_t bf[4][2];
#pragma unroll
            for (int t = 0; t < 4; t++) {
                int n0 = wn + t * 8 + grp;
                bf[t][0] = __float_as_uint(ws[n0 * VG_LDS + kk + qid]);
                bf[t][1] = __float_as_uint(ws[n0 * VG_LDS + kk + qid + 4]);
            }
#pragma unroll
            for (int i = 0; i < 4; i++)
#pragma unroll
                for (int j = 0; j < 4; j++) {
                    asm volatile(
                        "mma.sync.aligned.m16n8k8.row.col.f32.tf32.tf32.f32 "
                        "{%0,%1,%2,%3}, {%4,%5,%6,%7}, {%8,%9}, {%0,%1,%2,%3};"
                        : "+f"(acc[i][j][0]), "+f"(acc[i][j][1]),
                          "+f"(acc[i][j][2]), "+f"(acc[i][j][3])
                        : "r"(af[i][0]), "r"(af[i][1]), "r"(af[i][2]), "r"(af[i][3]),
                          "r"(bf[j][0]), "r"(bf[j][1]));
                }
        }
        __syncthreads();
    }

    // Epilogue: fused bias, vectorized float2 stores
#pragma unroll
    for (int i = 0; i < 4; i++) {
        int m0 = wm + i * 16 + grp;
#pragma unroll
        for (int j = 0; j < 4; j++) {
            int n = bn0 + wn + j * 8 + 2 * qid;
            if (n < Vv) {
                float2 b2 = *(const float2*)&bias[n];
                float2 v0 = make_float2(acc[i][j][0] + b2.x, acc[i][j][1] + b2.y);
                float2 v1 = make_float2(acc[i][j][2] + b2.x, acc[i][j][3] + b2.y);
                *(float2*)&Cl[(size_t)m0 * Vv + n] = v0;
                *(float2*)&Cl[(size_t)(m0 + 8) * Vv + n] = v1;
            }
        }
    }
}

// ---------------------------------------------------------------------------
// LSTM elementwise (float4 vectorized)
// ---------------------------------------------------------------------------
__global__ void lstm_kernel(const float* __restrict__ gates, const float* __restrict__ c0,
                            float* __restrict__ out) {
    int q = blockIdx.x * blockDim.x + threadIdx.x;   // 0..B*H/4
    if (q >= Bb * Hh / 4) return;
    int b = q >> 7;            // 128 float4 per row of H=512
    int h4 = (q & 127) << 2;
    const float* g = gates + (size_t)b * 4 * Hh;
    float4 gi = *(const float4*)&g[h4];
    float4 gf = *(const float4*)&g[512 + h4];
    float4 gg = *(const float4*)&g[1024 + h4];
    float4 go = *(const float4*)&g[1536 + h4];
    float4 cp = *(const float4*)&c0[(size_t)b * Hh + h4];
    float4 c, hh;
    c.x = sigmoid_fast(gf.x) * cp.x + sigmoid_fast(gi.x) * tanhf(gg.x);
    c.y = sigmoid_fast(gf.y) * cp.y + sigmoid_fast(gi.y) * tanhf(gg.y);
    c.z = sigmoid_fast(gf.z) * cp.z + sigmoid_fast(gi.z) * tanhf(gg.z);
    c.w = sigmoid_fast(gf.w) * cp.w + sigmoid_fast(gi.w) * tanhf(gg.w);
    hh.x = sigmoid_fast(go.x) * tanhf(c.x);
    hh.y = sigmoid_fast(go.y) * tanhf(c.y);
    hh.z = sigmoid_fast(go.z) * tanhf(c.z);
    hh.w = sigmoid_fast(go.w) * tanhf(c.w);
    *(float4*)&out[OFF_H + (size_t)b * Hh + h4] = hh;
    *(float4*)&out[OFF_C + (size_t)b * Hh + h4] = c;
}

// ---------------------------------------------------------------------------
// Attention scores
// ---------------------------------------------------------------------------
__global__ __launch_bounds__(256) void scores_kernel(
    const float* __restrict__ ef, const float* __restrict__ dec,
    const float* __restrict__ vw, const float* __restrict__ Wc,
    const float* __restrict__ cov, float* __restrict__ scores)
{
    __shared__ __align__(16) float s_dec[H2];
    __shared__ __align__(16) float s_v[H2];
    __shared__ __align__(16) float s_wc[H2];
    int b = blockIdx.y;
    int tid = threadIdx.x;
    for (int i = tid; i < H2; i += 256) {
        s_dec[i] = dec[(size_t)b * H2 + i];
        s_v[i] = vw[i];
        s_wc[i] = Wc[i];
    }
    __syncthreads();

    int warp = tid >> 5, lane = tid & 31;
    int t = blockIdx.x * 8 + warp;
    float cv = cov[(size_t)b * Tt + t];
    const float* p = ef + ((size_t)b * Tt + t) * H2;

    float acc = 0.0f;
#pragma unroll
    for (int i = 0; i < 8; i++) {
        int n = i * 128 + lane * 4;
        float4 e4 = *(const float4*)(p + n);
        acc += tanh_fast(e4.x + s_dec[n]     + cv * s_wc[n])     * s_v[n];
        acc += tanh_fast(e4.y + s_dec[n + 1] + cv * s_wc[n + 1]) * s_v[n + 1];
        acc += tanh_fast(e4.z + s_dec[n + 2] + cv * s_wc[n + 2]) * s_v[n + 2];
        acc += tanh_fast(e4.w + s_dec[n + 3] + cv * s_wc[n + 3]) * s_v[n + 3];
    }
#pragma unroll
    for (int o = 16; o > 0; o >>= 1) acc += __shfl_down_sync(0xffffffffu, acc, o);
    if (lane == 0) scores[(size_t)b * Tt + t] = acc;
}

// ---------------------------------------------------------------------------
// Fused: softmax over T (+mask renorm +coverage) -> c_t -> p_gen.
// grid = 128 (one block per b), 1024 threads.
// ---------------------------------------------------------------------------
__global__ __launch_bounds__(1024) void attn_fused_kernel(
    const float* __restrict__ scores, const float* __restrict__ mask,
    const float* __restrict__ cov, const float* __restrict__ eo,
    const float* __restrict__ x, const float* __restrict__ Wpg,
    const float* __restrict__ bpg, float* __restrict__ out)
{
    __shared__ float red[1024];
    __shared__ float sa[Tt];      // attn
    __shared__ float sct[H2];     // c_t

    int b = blockIdx.x, tid = threadIdx.x;

    // --- softmax over T=400 ---
    float s = (tid < Tt) ? scores[(size_t)b * Tt + tid] : -1e30f;
    red[tid] = s; __syncthreads();
    for (int st = 512; st > 0; st >>= 1) {
        if (tid < st) red[tid] = fmaxf(red[tid], red[tid + st]);
        __syncthreads();
    }
    float m = red[0]; __syncthreads();

    float e = (tid < Tt) ? __expf(s - m) : 0.0f;
    red[tid] = e; __syncthreads();
    for (int st = 512; st > 0; st >>= 1) {
        if (tid < st) red[tid] += red[tid + st];
        __syncthreads();
    }
    float S = red[0]; __syncthreads();

    float a = (tid < Tt) ? (e / S) * mask[(size_t)b * Tt + tid] : 0.0f;
    red[tid] = a; __syncthreads();
    for (int st = 512; st > 0; st >>= 1) {
        if (tid < st) red[tid] += red[tid + st];
        __syncthreads();
    }
    float S2 = red[0] + 1e-12f;

    float attn = a / S2;
    if (tid < Tt) {
        sa[tid] = attn;
        out[OFF_ATTN + (size_t)b * Tt + tid] = attn;
        out[OFF_COV  + (size_t)b * Tt + tid] = cov[(size_t)b * Tt + tid] + attn;
    }
    __syncthreads();

    // --- c_t[n] = sum_t sa[t] * eo[b,t,n];  n = tid (1024 threads == H2) ---
    const float* p = eo + (size_t)b * Tt * H2 + tid;
    float acc = 0.0f;
#pragma unroll 8
    for (int t = 0; t < Tt; t++) acc += sa[t] * p[(size_t)t * H2];
    sct[tid] = acc;
    out[OFF_CT + (size_t)b * H2 + tid] = acc;
    __syncthreads();

    // --- p_gen = sigmoid([c_t | h | c | x] . Wpg + b) ---
    float pacc = sct[tid] * Wpg[tid];
    if (tid < Hh) {
        pacc += out[OFF_H + (size_t)b * Hh + tid] * Wpg[1024 + tid];
    } else {
        int k = tid - Hh;
        pacc += out[OFF_C + (size_t)b * Hh + k] * Wpg[1536 + k];
    }
    if (tid < Ee) pacc += x[(size_t)b * Ee + tid] * Wpg[2048 + tid];
    red[tid] = pacc; __syncthreads();
    for (int st = 512; st > 0; st >>= 1) {
        if (tid < st) red[tid] += red[tid + st];
        __syncthreads();
    }
    if (tid == 0) out[OFF_PGEN + b] = sigmoid_fast(red[0] + bpg[0]);
}

// ---------------------------------------------------------------------------
// Fused vocab softmax (online) + pointer scatter. grid = 128, 1024 threads.
// ---------------------------------------------------------------------------
__global__ __launch_bounds__(1024) void vsoftmax_scatter_kernel(
    const float* __restrict__ logits, const int* __restrict__ ebev,
    float* __restrict__ out)
{
    __shared__ float smx[1024];
    __shared__ float ssm[1024];
    int b = blockIdx.x, tid = threadIdx.x;
    const float* L = logits + (size_t)b * Vv;

    float m = -1e30f, s = 0.0f;
    for (int j = tid; j < Vv; j += 1024) {
        float v = L[j];
        float nm = fmaxf(m, v);
        s = s * __expf(m - nm) + __expf(v - nm);
        m = nm;
    }
    smx[tid] = m; ssm[tid] = s; __syncthreads();
    for (int st = 512; st > 0; st >>= 1) {
        if (tid < st) {
            float m2 = smx[tid + st], s2 = ssm[tid + st];
            float m1 = smx[tid],      s1 = ssm[tid];
            float nm = fmaxf(m1, m2);
            ssm[tid] = s1 * __expf(m1 - nm) + s2 * __expf(m2 - nm);
            smx[tid] = nm;
        }
        __syncthreads();
    }
    float M = smx[0], S = ssm[0];

    float pg = out[OFF_PGEN + b];
    float scale = pg / S;
    float* F = out + (size_t)b * Vv;
    for (int j = tid; j < Vv; j += 1024) F[j] = __expf(L[j] - M) * scale;
    __syncthreads();   // F writes visible block-wide before scatter

    // scatter: F[ebev[b,t]] += (1-pg)*attn[b,t]
    if (tid < Tt) {
        float a = out[OFF_ATTN + (size_t)b * Tt + tid];
        atomicAdd(&F[ebev[(size_t)b * Tt + tid]], (1.0f - pg) * a);
    }
}

// ---------------------------------------------------------------------------
// Host launch
// ---------------------------------------------------------------------------
static void launch_gemm(const float* A1, int lda1, int K1, const float* W1, int ldw1,
                        const float* A2, int lda2, int K2, const float* W2, int ldw2,
                        const float* b1, const float* b2, float* C, int N, int ksplit)
{
    int steps = (K1 + K2) >> 4;
    int kchunk = (steps + ksplit - 1) / ksplit;
    int ky = (steps + kchunk - 1) / kchunk;
    dim3 grid((N + BN - 1) / BN, ky);
    gemm_bt<<<grid, 256>>>(A1, lda1, K1, W1, ldw1, A2, lda2, K2, W2, ldw2,
                           b1, b2, C, N, kchunk, (ky > 1) ? 1 : 0);
}

extern "C" void kernel_launch(void* const* d_in, const int* in_sizes, int n_in,
                              void* d_out_v, int out_size)
{
    (void)in_sizes; (void)n_in; (void)out_size;
    const int*   y    = (const int*)  d_in[0];
    const float* h0   = (const float*)d_in[1];
    const float* c0   = (const float*)d_in[2];
    const float* ct1  = (const float*)d_in[3];
    const float* eo   = (const float*)d_in[4];
    const float* ef   = (const float*)d_in[5];
    const float* mask = (const float*)d_in[6];
    const int*   ebev = (const int*)  d_in[7];
    const float* cov  = (const float*)d_in[8];
    const float* emb  = (const float*)d_in[9];
    const float* W_c  = (const float*)d_in[10];
    const float* W_dp = (const float*)d_in[11];
    const float* b_dp = (const float*)d_in[12];
    const float* v_w  = (const float*)d_in[13];
    const float* W_xc = (const float*)d_in[14];
    const float* b_xc = (const float*)d_in[15];
    const float* W_ih = (const float*)d_in[16];
    const float* W_hh = (const float*)d_in[17];
    const float* b_ih = (const float*)d_in[18];
    const float* b_hh = (const float*)d_in[19];
    const float* W_pg = (const float*)d_in[20];
    const float* b_pg = (const float*)d_in[21];
    const float* W_o1 = (const float*)d_in[22];
    const float* b_o1 = (const float*)d_in[23];
    const float* W_o2 = (const float*)d_in[24];
    const float* b_o2 = (const float*)d_in[25];
    float* out = (float*)d_out_v;

    float *p_yemb, *p_x, *p_gates, *p_dec, *p_scores, *p_o1, *p_logits;
    cudaGetSymbolAddress((void**)&p_yemb,   g_yemb);
    cudaGetSymbolAddress((void**)&p_x,      g_x);
    cudaGetSymbolAddress((void**)&p_gates,  g_gates);
    cudaGetSymbolAddress((void**)&p_dec,    g_decfea);
    cudaGetSymbolAddress((void**)&p_scores, g_scores);
    cudaGetSymbolAddress((void**)&p_o1,     g_o1);
    cudaGetSymbolAddress((void**)&p_logits, g_logits);

    cudaFuncSetAttribute(vocab_gemm_mma, cudaFuncAttributeMaxDynamicSharedMemorySize,
                         VG_SMEM_BYTES);

    // 1. embedding gather
    embed_kernel<<<(Bb * Ee + 255) / 256, 256>>>(y, emb, p_yemb);

    // 2. x = [c_t_1 | y_emb] @ W_xc^T + b_xc
    cudaMemsetAsync(p_x, 0, sizeof(float) * Bb * Ee, 0);
    launch_gemm(ct1, H2, H2, W_xc, 1152,
                p_yemb, Ee, Ee, W_xc + 1024, 1152,
                b_xc, nullptr, p_x, Ee, 36);

    // 3. gates = x @ W_ih^T + h0 @ W_hh^T + b_ih + b_hh
    cudaMemsetAsync(p_gates, 0, sizeof(float) * Bb * 4 * Hh, 0);
    launch_gemm(p_x, Ee, Ee, W_ih, Ee,
                h0, Hh, Hh, W_hh, Hh,
                b_ih, b_hh, p_gates, 4 * Hh, 8);

    // 4. LSTM cell
    lstm_kernel<<<(Bb * Hh / 4 + 255) / 256, 256>>>(p_gates, c0, out);

    // 5. dec_fea = [h | c] @ W_dp^T + b_dp
    cudaMemsetAsync(p_dec, 0, sizeof(float) * Bb * H2, 0);
    launch_gemm(out + OFF_H, Hh, Hh, W_dp, H2,
                out + OFF_C, Hh, Hh, W_dp + 512, H2,
                b_dp, nullptr, p_dec, H2, 8);

    // 6. attention scores
    scores_kernel<<<dim3(Tt / 8, Bb), 256>>>(ef, p_dec, v_w, W_c, cov, p_scores);

    // 7. fused softmax + c_t + p_gen (+ coverage, attn writes)
    attn_fused_kernel<<<Bb, 1024>>>(p_scores, mask, cov, eo, p_x, W_pg, b_pg, out);

    // 8. o1 = [h | c_t] @ W_o1^T + b_o1
    cudaMemsetAsync(p_o1, 0, sizeof(float) * Bb * Hh, 0);
    launch_gemm(out + OFF_H, Hh, Hh, W_o1, 3 * Hh,
                out + OFF_CT, H2, H2, W_o1 + 512, 3 * Hh,
                b_o1, nullptr, p_o1, Hh, 16);

    // 9. logits via warp-MMA tf32 GEMM, 4-stage cp.async pipeline (391 CTAs)
    vocab_gemm_mma<<<(Vv + 127) / 128, 256, VG_SMEM_BYTES>>>(p_o1, W_o2, b_o2, p_logits);

    // 10. fused vocab softmax + pointer scatter
    vsoftmax_scatter_kernel<<<Bb, 1024>>>(p_logits, ebev, out);
}

// round 6
// speedup vs baseline: 1.6448x; 1.0221x over previous
#include <cuda_runtime.h>
#include <math.h>
#include <stdint.h>

// Problem constants
#define Bb 128
#define Tt 400
#define Hh 512
#define H2 1024
#define Ee 128
#define Vv 50000

// Output layout (concatenated reference tuple, row-major each)
#define OFF_FINAL 0L
#define OFF_H     6400000L
#define OFF_C     6465536L
#define OFF_CT    6531072L
#define OFF_ATTN  6662144L
#define OFF_PGEN  6713344L
#define OFF_COV   6713472L

// Scratch (device globals: allowed; no runtime allocation)
__device__ float g_x[Bb * Ee];
__device__ float g_gates[Bb * 4 * Hh];
__device__ float g_decfea[Bb * H2];
__device__ float g_scores[Bb * Tt];
__device__ float g_o1[Bb * Hh];
__device__ float g_pgacc[Bb];
__device__ float g_logits[(size_t)Bb * Vv];

__device__ __forceinline__ float tanh_fast(float x) {
    float y;
    asm("tanh.approx.f32 %0, %1;" : "=f"(y) : "f"(x));
    return y;
}
__device__ __forceinline__ float sigmoid_fast(float x) {
    return 1.0f / (1.0f + __expf(-x));
}

// ---------------------------------------------------------------------------
// Zero scratch accumulators (single kernel replaces 4 memset nodes)
// ---------------------------------------------------------------------------
__global__ void zero_kernel(float* __restrict__ x, float* __restrict__ gates,
                            float* __restrict__ dec, float* __restrict__ o1,
                            float* __restrict__ pg)
{
    int i = blockIdx.x * blockDim.x + threadIdx.x;
    int stride = gridDim.x * blockDim.x;
    for (int j = i; j < Bb * Ee; j += stride) x[j] = 0.0f;
    for (int j = i; j < Bb * 4 * Hh; j += stride) gates[j] = 0.0f;
    for (int j = i; j < Bb * H2; j += stride) dec[j] = 0.0f;
    for (int j = i; j < Bb * Hh; j += stride) o1[j] = 0.0f;
    if (i < Bb) pg[i] = 0.0f;
}

// ---------------------------------------------------------------------------
// Generic small GEMM (FFMA): C[128,N] (+)= A1@W1^T + A2@W2^T + bias, K-split.
// Optional a2_idx: row indirection for A2 (fused embedding gather).
// ---------------------------------------------------------------------------
#define BM 128
#define BN 64
#define BK 16

__global__ __launch_bounds__(256) void gemm_bt(
    const float* __restrict__ A1, int lda1, int K1,
    const float* __restrict__ W1, int ldw1,
    const float* __restrict__ A2, int lda2, int K2,
    const float* __restrict__ W2, int ldw2,
    const int* __restrict__ a2_idx,
    const float* __restrict__ bias1, const float* __restrict__ bias2,
    float* __restrict__ C, int N, int kchunk, int split)
{
    __shared__ __align__(16) float As[BK][BM + 4];
    __shared__ __align__(16) float Ws[BK][BN + 4];

    int tid = threadIdx.x;
    int tx = tid & 15;
    int ty = tid >> 4;
    int bn0 = blockIdx.x * BN;

    int steps_total = (K1 + K2) >> 4;
    int s0 = blockIdx.y * kchunk;
    int s1 = min(s0 + kchunk, steps_total);
    if (s0 >= steps_total) return;

    float acc[8][4];
#pragma unroll
    for (int i = 0; i < 8; i++)
#pragma unroll
        for (int j = 0; j < 4; j++) acc[i][j] = 0.0f;

    int a_row = tid >> 2;
    int a_c4 = (tid & 3) * 4;

    for (int s = s0; s < s1; ++s) {
        int kk = s << 4;
        const float* Ap; int lda; int ko;
        const float* Wp; int ldw;
        bool ind = false;
        if (kk < K1) { Ap = A1; lda = lda1; ko = kk;      Wp = W1; ldw = ldw1; }
        else         { Ap = A2; lda = lda2; ko = kk - K1; Wp = W2; ldw = ldw2;
                       ind = (a2_idx != nullptr); }

        {
            int r1 = a_row;
            int r2 = a_row + 64;
            size_t off1 = ind ? (size_t)a2_idx[r1] * lda : (size_t)r1 * lda;
            size_t off2 = ind ? (size_t)a2_idx[r2] * lda : (size_t)r2 * lda;
            float4 v = *(const float4*)&Ap[off1 + ko + a_c4];
            As[a_c4 + 0][r1] = v.x; As[a_c4 + 1][r1] = v.y;
            As[a_c4 + 2][r1] = v.z; As[a_c4 + 3][r1] = v.w;
            float4 v2 = *(const float4*)&Ap[off2 + ko + a_c4];
            As[a_c4 + 0][r2] = v2.x; As[a_c4 + 1][r2] = v2.y;
            As[a_c4 + 2][r2] = v2.z; As[a_c4 + 3][r2] = v2.w;
        }
        {
            int n = a_row;
            float4 v = make_float4(0.f, 0.f, 0.f, 0.f);
            if (bn0 + n < N)
                v = *(const float4*)&Wp[(size_t)(bn0 + n) * ldw + ko + a_c4];
            Ws[a_c4 + 0][n] = v.x; Ws[a_c4 + 1][n] = v.y;
            Ws[a_c4 + 2][n] = v.z; Ws[a_c4 + 3][n] = v.w;
        }
        __syncthreads();

#pragma unroll
        for (int k = 0; k < BK; k++) {
            float4 a0 = *(const float4*)&As[k][ty * 8];
            float4 a1 = *(const float4*)&As[k][ty * 8 + 4];
            float4 w  = *(const float4*)&Ws[k][tx * 4];
            float am[8] = {a0.x, a0.y, a0.z, a0.w, a1.x, a1.y, a1.z, a1.w};
            float wn[4] = {w.x, w.y, w.z, w.w};
#pragma unroll
            for (int i = 0; i < 8; i++)
#pragma unroll
                for (int j = 0; j < 4; j++) acc[i][j] += am[i] * wn[j];
        }
        __syncthreads();
    }

    bool addb = (blockIdx.y == 0);
#pragma unroll
    for (int i = 0; i < 8; i++) {
        int m = ty * 8 + i;
#pragma unroll
        for (int j = 0; j < 4; j++) {
            int n = bn0 + tx * 4 + j;
            if (n < N) {
                float v = acc[i][j];
                if (addb) {
                    if (bias1) v += bias1[n];
                    if (bias2) v += bias2[n];
                }
                if (split) atomicAdd(&C[(size_t)m * N + n], v);
                else       C[(size_t)m * N + n] = v;
            }
        }
    }
}

// ---------------------------------------------------------------------------
// Vocab GEMM via warp-level tf32 MMA + 4-stage cp.async pipeline:
// logits[128, 50000] = o1[128,512] @ W_o2[50000,512]^T + b_o2
// ---------------------------------------------------------------------------
#define VG_LDS 20
#define VG_STAGEF (128 * VG_LDS)
#define VG_STAGEB (VG_STAGEF * 4)
#define VG_STAGES 4
#define VG_SMEM_BYTES (VG_STAGES * VG_STAGEB * 2)

__device__ __forceinline__ uint32_t smem_u32(const void* p) {
    return (uint32_t)__cvta_generic_to_shared(p);
}

__device__ __forceinline__ void vg_prefetch(
    int s, int stage, const float* __restrict__ A, const float* __restrict__ W,
    int bn0, uint32_t sA, uint32_t sW)
{
    int ck = s * 16;
    int tid = threadIdx.x;
#pragma unroll
    for (int i = 0; i < 2; i++) {
        int slot = i * 256 + tid;
        int row = slot >> 2;
        int c4 = (slot & 3) << 2;
        uint32_t soff = (uint32_t)(stage * VG_STAGEB + (row * VG_LDS + c4) * 4);
        asm volatile("cp.async.cg.shared.global [%0], [%1], 16;"
                     :: "r"(sA + soff), "l"(A + row * 512 + ck + c4) : "memory");
        int nrow = bn0 + row;
        if (nrow < Vv)
            asm volatile("cp.async.cg.shared.global [%0], [%1], 16;"
                         :: "r"(sW + soff), "l"(W + (size_t)nrow * 512 + ck + c4) : "memory");
    }
    asm volatile("cp.async.commit_group;" ::: "memory");
}

__global__ __launch_bounds__(256) void vocab_gemm_mma(
    const float* __restrict__ A, const float* __restrict__ W,
    const float* __restrict__ bias, float* __restrict__ Cl)
{
    extern __shared__ __align__(16) float vgsm[];
    float* As = vgsm;
    float* Ws = vgsm + VG_STAGES * VG_STAGEF;

    int tid = threadIdx.x;
    int lane = tid & 31;
    int wid = tid >> 5;
    int wm = (wid & 1) * 64;
    int wn = (wid >> 1) * 32;
    int bn0 = blockIdx.x * 128;

    int grp = lane >> 2;
    int qid = lane & 3;

    uint32_t sA = smem_u32(As);
    uint32_t sW = smem_u32(Ws);

    if (bn0 + 128 > Vv) {
#pragma unroll
        for (int st = 0; st < VG_STAGES; st++)
            for (int slot = tid; slot < 512; slot += 256) {
                int row = slot >> 2;
                int c4 = (slot & 3) << 2;
                if (bn0 + row >= Vv)
                    *(float4*)&Ws[st * VG_STAGEF + row * VG_LDS + c4] =
                        make_float4(0.f, 0.f, 0.f, 0.f);
            }
        __syncthreads();
    }

    float acc[4][4][4];
#pragma unroll
    for (int i = 0; i < 4; i++)
#pragma unroll
        for (int j = 0; j < 4; j++)
#pragma unroll
            for (int r = 0; r < 4; r++) acc[i][j][r] = 0.0f;

    vg_prefetch(0, 0, A, W, bn0, sA, sW);
    vg_prefetch(1, 1, A, W, bn0, sA, sW);
    vg_prefetch(2, 2, A, W, bn0, sA, sW);

    for (int s = 0; s < 32; s++) {
        int stage = s & 3;
        if (s < 29) {
            vg_prefetch(s + 3, (s + 3) & 3, A, W, bn0, sA, sW);
            asm volatile("cp.async.wait_group 3;" ::: "memory");
        } else if (s == 29) {
            asm volatile("cp.async.wait_group 2;" ::: "memory");
        } else if (s == 30) {
            asm volatile("cp.async.wait_group 1;" ::: "memory");
        } else {
            asm volatile("cp.async.wait_group 0;" ::: "memory");
        }
        __syncthreads();

        const float* as = As + stage * VG_STAGEF;
        const float* ws = Ws + stage * VG_STAGEF;

#pragma unroll
        for (int k8 = 0; k8 < 2; k8++) {
            int kk = k8 * 8;
            uint32_t af[4][4];
#pragma unroll
            for (int t = 0; t < 4; t++) {
                int r0 = wm + t * 16 + grp;
                af[t][0] = __float_as_uint(as[r0 * VG_LDS + kk + qid]);
                af[t][1] = __float_as_uint(as[(r0 + 8) * VG_LDS + kk + qid]);
                af[t][2] = __float_as_uint(as[r0 * VG_LDS + kk + qid + 4]);
                af[t][3] = __float_as_uint(as[(r0 + 8) * VG_LDS + kk + qid + 4]);
            }
            uint32_t bf[4][2];
#pragma unroll
            for (int t = 0; t < 4; t++) {
                int n0 = wn + t * 8 + grp;
                bf[t][0] = __float_as_uint(ws[n0 * VG_LDS + kk + qid]);
                bf[t][1] = __float_as_uint(ws[n0 * VG_LDS + kk + qid + 4]);
            }
#pragma unroll
            for (int i = 0; i < 4; i++)
#pragma unroll
                for (int j = 0; j < 4; j++) {
                    asm volatile(
                        "mma.sync.aligned.m16n8k8.row.col.f32.tf32.tf32.f32 "
                        "{%0,%1,%2,%3}, {%4,%5,%6,%7}, {%8,%9}, {%0,%1,%2,%3};"
                        : "+f"(acc[i][j][0]), "+f"(acc[i][j][1]),
                          "+f"(acc[i][j][2]), "+f"(acc[i][j][3])
                        : "r"(af[i][0]), "r"(af[i][1]), "r"(af[i][2]), "r"(af[i][3]),
                          "r"(bf[j][0]), "r"(bf[j][1]));
                }
        }
        __syncthreads();
    }

#pragma unroll
    for (int i = 0; i < 4; i++) {
        int m0 = wm + i * 16 + grp;
#pragma unroll
        for (int j = 0; j < 4; j++) {
            int n = bn0 + wn + j * 8 + 2 * qid;
            if (n < Vv) {
                float2 b2 = *(const float2*)&bias[n];
                float2 v0 = make_float2(acc[i][j][0] + b2.x, acc[i][j][1] + b2.y);
                float2 v1 = make_float2(acc[i][j][2] + b2.x, acc[i][j][3] + b2.y);
                *(float2*)&Cl[(size_t)m0 * Vv + n] = v0;
                *(float2*)&Cl[(size_t)(m0 + 8) * Vv + n] = v1;
            }
        }
    }
}

// ---------------------------------------------------------------------------
// LSTM elementwise (float4 vectorized)
// ---------------------------------------------------------------------------
__global__ void lstm_kernel(const float* __restrict__ gates, const float* __restrict__ c0,
                            float* __restrict__ out) {
    int q = blockIdx.x * blockDim.x + threadIdx.x;
    if (q >= Bb * Hh / 4) return;
    int b = q >> 7;
    int h4 = (q & 127) << 2;
    const float* g = gates + (size_t)b * 4 * Hh;
    float4 gi = *(const float4*)&g[h4];
    float4 gf = *(const float4*)&g[512 + h4];
    float4 gg = *(const float4*)&g[1024 + h4];
    float4 go = *(const float4*)&g[1536 + h4];
    float4 cp = *(const float4*)&c0[(size_t)b * Hh + h4];
    float4 c, hh;
    c.x = sigmoid_fast(gf.x) * cp.x + sigmoid_fast(gi.x) * tanhf(gg.x);
    c.y = sigmoid_fast(gf.y) * cp.y + sigmoid_fast(gi.y) * tanhf(gg.y);
    c.z = sigmoid_fast(gf.z) * cp.z + sigmoid_fast(gi.z) * tanhf(gg.z);
    c.w = sigmoid_fast(gf.w) * cp.w + sigmoid_fast(gi.w) * tanhf(gg.w);
    hh.x = sigmoid_fast(go.x) * tanhf(c.x);
    hh.y = sigmoid_fast(go.y) * tanhf(c.y);
    hh.z = sigmoid_fast(go.z) * tanhf(c.z);
    hh.w = sigmoid_fast(go.w) * tanhf(c.w);
    *(float4*)&out[OFF_H + (size_t)b * Hh + h4] = hh;
    *(float4*)&out[OFF_C + (size_t)b * Hh + h4] = c;
}

// ---------------------------------------------------------------------------
// Attention scores
// ---------------------------------------------------------------------------
__global__ __launch_bounds__(256) void scores_kernel(
    const float* __restrict__ ef, const float* __restrict__ dec,
    const float* __restrict__ vw, const float* __restrict__ Wc,
    const float* __restrict__ cov, float* __restrict__ scores)
{
    __shared__ __align__(16) float s_dec[H2];
    __shared__ __align__(16) float s_v[H2];
    __shared__ __align__(16) float s_wc[H2];
    int b = blockIdx.y;
    int tid = threadIdx.x;
    for (int i = tid; i < H2; i += 256) {
        s_dec[i] = dec[(size_t)b * H2 + i];
        s_v[i] = vw[i];
        s_wc[i] = Wc[i];
    }
    __syncthreads();

    int warp = tid >> 5, lane = tid & 31;
    int t = blockIdx.x * 8 + warp;
    float cv = cov[(size_t)b * Tt + t];
    const float* p = ef + ((size_t)b * Tt + t) * H2;

    float acc = 0.0f;
#pragma unroll
    for (int i = 0; i < 8; i++) {
        int n = i * 128 + lane * 4;
        float4 e4 = *(const float4*)(p + n);
        acc += tanh_fast(e4.x + s_dec[n]     + cv * s_wc[n])     * s_v[n];
        acc += tanh_fast(e4.y + s_dec[n + 1] + cv * s_wc[n + 1]) * s_v[n + 1];
        acc += tanh_fast(e4.z + s_dec[n + 2] + cv * s_wc[n + 2]) * s_v[n + 2];
        acc += tanh_fast(e4.w + s_dec[n + 3] + cv * s_wc[n + 3]) * s_v[n + 3];
    }
#pragma unroll
    for (int o = 16; o > 0; o >>= 1) acc += __shfl_down_sync(0xffffffffu, acc, o);
    if (lane == 0) scores[(size_t)b * Tt + t] = acc;
}

// ---------------------------------------------------------------------------
// Fused attention: softmax over T (+mask renorm +coverage), half of c_t,
// partial p_gen dot (atomicAdd into g_pgacc).
// grid = (2, 128), 512 threads. blockIdx.x = column half, blockIdx.y = b.
// Softmax recomputed redundantly in both halves (cheap).
// ---------------------------------------------------------------------------
__global__ __launch_bounds__(512) void attn_fused_kernel(
    const float* __restrict__ scores, const float* __restrict__ mask,
    const float* __restrict__ cov, const float* __restrict__ eo,
    const float* __restrict__ x, const float* __restrict__ Wpg,
    float* __restrict__ pgacc, float* __restrict__ out)
{
    __shared__ float red[512];
    __shared__ float sa[Tt];

    int b = blockIdx.y, hx = blockIdx.x, tid = threadIdx.x;

    // --- softmax over T=400 ---
    float s = (tid < Tt) ? scores[(size_t)b * Tt + tid] : -1e30f;
    red[tid] = s; __syncthreads();
    for (int st = 256; st > 0; st >>= 1) {
        if (tid < st) red[tid] = fmaxf(red[tid], red[tid + st]);
        __syncthreads();
    }
    float m = red[0]; __syncthreads();

    float e = (tid < Tt) ? __expf(s - m) : 0.0f;
    red[tid] = e; __syncthreads();
    for (int st = 256; st > 0; st >>= 1) {
        if (tid < st) red[tid] += red[tid + st];
        __syncthreads();
    }
    float S = red[0]; __syncthreads();

    float a = (tid < Tt) ? (e / S) * mask[(size_t)b * Tt + tid] : 0.0f;
    red[tid] = a; __syncthreads();
    for (int st = 256; st > 0; st >>= 1) {
        if (tid < st) red[tid] += red[tid + st];
        __syncthreads();
    }
    float S2 = red[0] + 1e-12f;

    float attn = a / S2;
    if (tid < Tt) {
        sa[tid] = attn;
        if (hx == 0) {
            out[OFF_ATTN + (size_t)b * Tt + tid] = attn;
            out[OFF_COV  + (size_t)b * Tt + tid] = cov[(size_t)b * Tt + tid] + attn;
        }
    }
    __syncthreads();

    // --- c_t half: n = hx*512 + tid ---
    int n = hx * 512 + tid;
    const float* p = eo + (size_t)b * Tt * H2 + n;
    float acc = 0.0f;
#pragma unroll 8
    for (int t = 0; t < Tt; t++) acc += sa[t] * p[(size_t)t * H2];
    out[OFF_CT + (size_t)b * H2 + n] = acc;

    // --- partial p_gen: this half's c_t terms + (h or c) terms + x terms ---
    float pacc = acc * Wpg[n];
    if (hx == 0) {
        pacc += out[OFF_H + (size_t)b * Hh + tid] * Wpg[1024 + tid];
        if (tid < Ee) pacc += x[(size_t)b * Ee + tid] * Wpg[2048 + tid];
    } else {
        pacc += out[OFF_C + (size_t)b * Hh + tid] * Wpg[1536 + tid];
    }
    red[tid] = pacc; __syncthreads();
    for (int st = 256; st > 0; st >>= 1) {
        if (tid < st) red[tid] += red[tid + st];
        __syncthreads();
    }
    if (tid == 0) atomicAdd(&pgacc[b], red[0]);
}

// ---------------------------------------------------------------------------
// Fused vocab softmax (online) + p_gen finalize + pointer scatter.
// grid = 128, 1024 threads.
// ---------------------------------------------------------------------------
__global__ __launch_bounds__(1024) void vsoftmax_scatter_kernel(
    const float* __restrict__ logits, const int* __restrict__ ebev,
    const float* __restrict__ pgacc, const float* __restrict__ bpg,
    float* __restrict__ out)
{
    __shared__ float smx[1024];
    __shared__ float ssm[1024];
    int b = blockIdx.x, tid = threadIdx.x;
    const float* L = logits + (size_t)b * Vv;

    float m = -1e30f, s = 0.0f;
    for (int j = tid; j < Vv; j += 1024) {
        float v = L[j];
        float nm = fmaxf(m, v);
        s = s * __expf(m - nm) + __expf(v - nm);
        m = nm;
    }
    smx[tid] = m; ssm[tid] = s; __syncthreads();
    for (int st = 512; st > 0; st >>= 1) {
        if (tid < st) {
            float m2 = smx[tid + st], s2 = ssm[tid + st];
            float m1 = smx[tid],      s1 = ssm[tid];
            float nm = fmaxf(m1, m2);
            ssm[tid] = s1 * __expf(m1 - nm) + s2 * __expf(m2 - nm);
            smx[tid] = nm;
        }
        __syncthreads();
    }
    float M = smx[0], S = ssm[0];

    float pg = sigmoid_fast(pgacc[b] + bpg[0]);
    if (tid == 0) out[OFF_PGEN + b] = pg;

    float scale = pg / S;
    float* F = out + (size_t)b * Vv;
    for (int j = tid; j < Vv; j += 1024) F[j] = __expf(L[j] - M) * scale;
    __syncthreads();

    if (tid < Tt) {
        float a = out[OFF_ATTN + (size_t)b * Tt + tid];
        atomicAdd(&F[ebev[(size_t)b * Tt + tid]], (1.0f - pg) * a);
    }
}

// ---------------------------------------------------------------------------
// Host launch
// ---------------------------------------------------------------------------
static void launch_gemm(const float* A1, int lda1, int K1, const float* W1, int ldw1,
                        const float* A2, int lda2, int K2, const float* W2, int ldw2,
                        const int* a2_idx,
                        const float* b1, const float* b2, float* C, int N, int ksplit)
{
    int steps = (K1 + K2) >> 4;
    int kchunk = (steps + ksplit - 1) / ksplit;
    int ky = (steps + kchunk - 1) / kchunk;
    dim3 grid((N + BN - 1) / BN, ky);
    gemm_bt<<<grid, 256>>>(A1, lda1, K1, W1, ldw1, A2, lda2, K2, W2, ldw2,
                           a2_idx, b1, b2, C, N, kchunk, (ky > 1) ? 1 : 0);
}

extern "C" void kernel_launch(void* const* d_in, const int* in_sizes, int n_in,
                              void* d_out_v, int out_size)
{
    (void)in_sizes; (void)n_in; (void)out_size;
    const int*   y    = (const int*)  d_in[0];
    const float* h0   = (const float*)d_in[1];
    const float* c0   = (const float*)d_in[2];
    const float* ct1  = (const float*)d_in[3];
    const float* eo   = (const float*)d_in[4];
    const float* ef   = (const float*)d_in[5];
    const float* mask = (const float*)d_in[6];
    const int*   ebev = (const int*)  d_in[7];
    const float* cov  = (const float*)d_in[8];
    const float* emb  = (const float*)d_in[9];
    const float* W_c  = (const float*)d_in[10];
    const float* W_dp = (const float*)d_in[11];
    const float* b_dp = (const float*)d_in[12];
    const float* v_w  = (const float*)d_in[13];
    const float* W_xc = (const float*)d_in[14];
    const float* b_xc = (const float*)d_in[15];
    const float* W_ih = (const float*)d_in[16];
    const float* W_hh = (const float*)d_in[17];
    const float* b_ih = (const float*)d_in[18];
    const float* b_hh = (const float*)d_in[19];
    const float* W_pg = (const float*)d_in[20];
    const float* b_pg = (const float*)d_in[21];
    const float* W_o1 = (const float*)d_in[22];
    const float* b_o1 = (const float*)d_in[23];
    const float* W_o2 = (const float*)d_in[24];
    const float* b_o2 = (const float*)d_in[25];
    float* out = (float*)d_out_v;

    float *p_x, *p_gates, *p_dec, *p_scores, *p_o1, *p_logits, *p_pgacc;
    cudaGetSymbolAddress((void**)&p_x,      g_x);
    cudaGetSymbolAddress((void**)&p_gates,  g_gates);
    cudaGetSymbolAddress((void**)&p_dec,    g_decfea);
    cudaGetSymbolAddress((void**)&p_scores, g_scores);
    cudaGetSymbolAddress((void**)&p_o1,     g_o1);
    cudaGetSymbolAddress((void**)&p_logits, g_logits);
    cudaGetSymbolAddress((void**)&p_pgacc,  g_pgacc);

    cudaFuncSetAttribute(vocab_gemm_mma, cudaFuncAttributeMaxDynamicSharedMemorySize,
                         VG_SMEM_BYTES);

    // 0. zero scratch accumulators (one kernel, replaces 4 memsets)
    zero_kernel<<<160, 256>>>(p_x, p_gates, p_dec, p_o1, p_pgacc);

    // 1. x = [c_t_1 | emb[y]] @ W_xc^T + b_xc  (embedding gather fused via a2_idx)
    launch_gemm(ct1, H2, H2, W_xc, 1152,
                emb, Ee, Ee, W_xc + 1024, 1152, y,
                b_xc, nullptr, p_x, Ee, 36);

    // 2. gates = x @ W_ih^T + h0 @ W_hh^T + b_ih + b_hh
    launch_gemm(p_x, Ee, Ee, W_ih, Ee,
                h0, Hh, Hh, W_hh, Hh, nullptr,
                b_ih, b_hh, p_gates, 4 * Hh, 8);

    // 3. LSTM cell
    lstm_kernel<<<(Bb * Hh / 4 + 255) / 256, 256>>>(p_gates, c0, out);

    // 4. dec_fea = [h | c] @ W_dp^T + b_dp
    launch_gemm(out + OFF_H, Hh, Hh, W_dp, H2,
                out + OFF_C, Hh, Hh, W_dp + 512, H2, nullptr,
                b_dp, nullptr, p_dec, H2, 8);

    // 5. attention scores
    scores_kernel<<<dim3(Tt / 8, Bb), 256>>>(ef, p_dec, v_w, W_c, cov, p_scores);

    // 6. fused softmax + c_t halves + partial p_gen
    attn_fused_kernel<<<dim3(2, Bb), 512>>>(p_scores, mask, cov, eo, p_x, W_pg,
                                            p_pgacc, out);

    // 7. o1 = [h | c_t] @ W_o1^T + b_o1
    launch_gemm(out + OFF_H, Hh, Hh, W_o1, 3 * Hh,
                out + OFF_CT, H2, H2, W_o1 + 512, 3 * Hh, nullptr,
                b_o1, nullptr, p_o1, Hh, 16);

    // 8. logits via warp-MMA tf32 GEMM, 4-stage cp.async pipeline (391 CTAs)
    vocab_gemm_mma<<<(Vv + 127) / 128, 256, VG_SMEM_BYTES>>>(p_o1, W_o2, b_o2, p_logits);

    // 9. fused vocab softmax + p_gen finalize + pointer scatter
    vsoftmax_scatter_kernel<<<Bb, 1024>>>(p_logits, ebev, p_pgacc, b_pg, out);
}